// round 14
// baseline (speedup 1.0000x reference)
#include <cuda_runtime.h>
#include <cuda_bf16.h>
#include <cstdint>

// Problem constants
#define NN   32768
#define FIN  128
#define CC   256
#define HH   4
#define FH   64
#define EE   524288
#define BB   64
#define NPG  512
#define EPG  (EE / BB)
#define K1   256
#define K2   128

// ---------------- scratch (device globals; no allocation allowed) ----------
__device__ float    g_hlin[NN * CC];        // GEMM outputs (fp32)
__device__ float    g_hout[NN * CC];        // gat2 output (fp32)
__device__ float    g_es[NN * HH];
__device__ float    g_ed[NN * HH];
__device__ int      g_off[NN + 1];
__device__ int      g_csrc[EE];
__device__ float    g_pool1[(BB * K1) * CC];
__device__ float    g_pool2[(BB * K2) * CC];
// pre-split tf32 hi/lo operand buffers
__device__ float    g_xh[NN * FIN];
__device__ float    g_xl[NN * FIN];
__device__ float    g_hh[NN * CC];
__device__ float    g_hl[NN * CC];
__device__ float    g_selh[(BB * K1) * CC];
__device__ float    g_sell[(BB * K1) * CC];
__device__ float    g_w1h[FIN * CC];
__device__ float    g_w1l[FIN * CC];
__device__ float    g_w2h[CC * CC];
__device__ float    g_w2l[CC * CC];
__device__ float    g_p1h[CC * CC];
__device__ float    g_p1l[CC * CC];
__device__ float    g_p2h[CC * CC];
__device__ float    g_p2l[CC * CC];

__device__ __forceinline__ float leaky(float x) { return x > 0.f ? x : 0.2f * x; }

// ---------------- tf32 helpers ----------------------------------------------
__device__ __forceinline__ float tf32r(float x) {
    uint32_t u;
    asm("cvt.rna.tf32.f32 %0, %1;" : "=r"(u) : "f"(x));
    return __uint_as_float(u);
}
__device__ __forceinline__ void split4(const float4 v, float4& h, float4& l) {
    h.x = tf32r(v.x); l.x = v.x - h.x;
    h.y = tf32r(v.y); l.y = v.y - h.y;
    h.z = tf32r(v.z); l.z = v.z - h.z;
    h.w = tf32r(v.w); l.w = v.w - h.w;
}
__device__ __forceinline__ void mma8(float4& d, const uint32_t* a, const uint32_t* b) {
    asm volatile("mma.sync.aligned.m16n8k8.row.col.f32.tf32.tf32.f32 "
        "{%0,%1,%2,%3}, {%4,%5,%6,%7}, {%8,%9}, {%0,%1,%2,%3};"
        : "+f"(d.x), "+f"(d.y), "+f"(d.z), "+f"(d.w)
        : "r"(a[0]), "r"(a[1]), "r"(a[2]), "r"(a[3]), "r"(b[0]), "r"(b[1]));
}

// ---------------- generic split kernel (x and weights) ----------------------
__global__ void split_kernel(const float* __restrict__ src, float* __restrict__ hi,
                             float* __restrict__ lo, int n4) {
    const int i = blockIdx.x * blockDim.x + threadIdx.x;
    if (i >= n4) return;
    float4 h, l;
    split4(((const float4*)src)[i], h, l);
    ((float4*)hi)[i] = h;
    ((float4*)lo)[i] = l;
}

// ---------------- 3xTF32 tensor-core GEMM with PRE-SPLIT inputs -------------
// C[M,N] = A@B (+bias). A/B given as tf32 hi/lo pairs; staging is pure
// LDG.128 -> STS.128 (no conversions in the hot loop). 128x128 CTA tile,
// 256 threads (2x4 warps of 64x32), BK=16. M%128==0, N%128==0, K%16==0.
#define ASTR 20
#define BSTR 136
__global__ void __launch_bounds__(256, 2)
tf32_gemm(const float* __restrict__ Ah, const float* __restrict__ Al,
          const float* __restrict__ Bh, const float* __restrict__ Bl,
          const float* __restrict__ bias, float* __restrict__ Cm,
          int M, int N, int K) {
    __shared__ float As_hi[128 * ASTR];
    __shared__ float As_lo[128 * ASTR];
    __shared__ float Bs_hi[16 * BSTR];
    __shared__ float Bs_lo[16 * BSTR];

    const int tid = threadIdx.x;
    const int lane = tid & 31, wid = tid >> 5;
    const int warp_m = wid & 1, warp_n = wid >> 1;
    const int g = lane >> 2, t = lane & 3;
    const int wm0 = warp_m * 64, wn0 = warp_n * 32;
    const int row0 = blockIdx.y * 128;
    const int col0 = blockIdx.x * 128;

    const int arow0 = tid >> 2, ac0 = (tid & 3) << 2;
    const int arow1 = arow0 + 64, ac1 = ac0;
    const int brow0 = tid >> 5, bc0 = (tid & 31) << 2;
    const int brow1 = brow0 + 8, bc1 = bc0;

    float4 acc[4][4];
#pragma unroll
    for (int i = 0; i < 4; i++)
#pragma unroll
        for (int j = 0; j < 4; j++) acc[i][j] = make_float4(0.f, 0.f, 0.f, 0.f);

    const int ntiles = K >> 4;
    float4 pah0, pah1, pal0, pal1, pbh0, pbh1, pbl0, pbl1;
    pah0 = *(const float4*)&Ah[(size_t)(row0 + arow0) * K + ac0];
    pah1 = *(const float4*)&Ah[(size_t)(row0 + arow1) * K + ac1];
    pal0 = *(const float4*)&Al[(size_t)(row0 + arow0) * K + ac0];
    pal1 = *(const float4*)&Al[(size_t)(row0 + arow1) * K + ac1];
    pbh0 = *(const float4*)&Bh[(size_t)brow0 * N + col0 + bc0];
    pbh1 = *(const float4*)&Bh[(size_t)brow1 * N + col0 + bc1];
    pbl0 = *(const float4*)&Bl[(size_t)brow0 * N + col0 + bc0];
    pbl1 = *(const float4*)&Bl[(size_t)brow1 * N + col0 + bc1];

    for (int kt = 0; kt < ntiles; kt++) {
        *(float4*)&As_hi[arow0 * ASTR + ac0] = pah0;
        *(float4*)&As_hi[arow1 * ASTR + ac1] = pah1;
        *(float4*)&As_lo[arow0 * ASTR + ac0] = pal0;
        *(float4*)&As_lo[arow1 * ASTR + ac1] = pal1;
        *(float4*)&Bs_hi[brow0 * BSTR + bc0] = pbh0;
        *(float4*)&Bs_hi[brow1 * BSTR + bc1] = pbh1;
        *(float4*)&Bs_lo[brow0 * BSTR + bc0] = pbl0;
        *(float4*)&Bs_lo[brow1 * BSTR + bc1] = pbl1;
        __syncthreads();
        if (kt + 1 < ntiles) {
            const int k0 = (kt + 1) << 4;
            pah0 = *(const float4*)&Ah[(size_t)(row0 + arow0) * K + k0 + ac0];
            pah1 = *(const float4*)&Ah[(size_t)(row0 + arow1) * K + k0 + ac1];
            pal0 = *(const float4*)&Al[(size_t)(row0 + arow0) * K + k0 + ac0];
            pal1 = *(const float4*)&Al[(size_t)(row0 + arow1) * K + k0 + ac1];
            pbh0 = *(const float4*)&Bh[(size_t)(k0 + brow0) * N + col0 + bc0];
            pbh1 = *(const float4*)&Bh[(size_t)(k0 + brow1) * N + col0 + bc1];
            pbl0 = *(const float4*)&Bl[(size_t)(k0 + brow0) * N + col0 + bc0];
            pbl1 = *(const float4*)&Bl[(size_t)(k0 + brow1) * N + col0 + bc1];
        }
        const uint32_t* AhS = (const uint32_t*)As_hi;
        const uint32_t* AlS = (const uint32_t*)As_lo;
        const uint32_t* BhS = (const uint32_t*)Bs_hi;
        const uint32_t* BlS = (const uint32_t*)Bs_lo;
#pragma unroll
        for (int k8 = 0; k8 < 16; k8 += 8) {
            uint32_t af[4][4], bh[4][2], bl[4][2];
#pragma unroll
            for (int nt = 0; nt < 4; nt++) {
                const int c = wn0 + nt * 8 + g;
                bh[nt][0] = BhS[(k8 + t) * BSTR + c];
                bh[nt][1] = BhS[(k8 + t + 4) * BSTR + c];
                bl[nt][0] = BlS[(k8 + t) * BSTR + c];
                bl[nt][1] = BlS[(k8 + t + 4) * BSTR + c];
            }
#pragma unroll
            for (int mt = 0; mt < 4; mt++) {
                const int r = wm0 + mt * 16 + g;
                af[mt][0] = AhS[r * ASTR + k8 + t];
                af[mt][1] = AhS[(r + 8) * ASTR + k8 + t];
                af[mt][2] = AhS[r * ASTR + k8 + t + 4];
                af[mt][3] = AhS[(r + 8) * ASTR + k8 + t + 4];
            }
#pragma unroll
            for (int mt = 0; mt < 4; mt++)
#pragma unroll
                for (int nt = 0; nt < 4; nt++) {
                    mma8(acc[mt][nt], af[mt], bh[nt]);
                    mma8(acc[mt][nt], af[mt], bl[nt]);
                }
#pragma unroll
            for (int mt = 0; mt < 4; mt++) {
                const int r = wm0 + mt * 16 + g;
                af[mt][0] = AlS[r * ASTR + k8 + t];
                af[mt][1] = AlS[(r + 8) * ASTR + k8 + t];
                af[mt][2] = AlS[r * ASTR + k8 + t + 4];
                af[mt][3] = AlS[(r + 8) * ASTR + k8 + t + 4];
            }
#pragma unroll
            for (int mt = 0; mt < 4; mt++)
#pragma unroll
                for (int nt = 0; nt < 4; nt++)
                    mma8(acc[mt][nt], af[mt], bh[nt]);
        }
        __syncthreads();
    }

#pragma unroll
    for (int nt = 0; nt < 4; nt++) {
        const int c = col0 + wn0 + nt * 8 + 2 * t;
        float2 bv = make_float2(0.f, 0.f);
        if (bias) bv = *(const float2*)&bias[c];
#pragma unroll
        for (int mt = 0; mt < 4; mt++) {
            const int r = row0 + wm0 + mt * 16 + g;
            float2 lo2 = make_float2(acc[mt][nt].x + bv.x, acc[mt][nt].y + bv.y);
            float2 hi2 = make_float2(acc[mt][nt].z + bv.x, acc[mt][nt].w + bv.y);
            *(float2*)&Cm[(size_t)r * N + c] = lo2;
            *(float2*)&Cm[(size_t)(r + 8) * N + c] = hi2;
        }
    }
}

// ---------------- single-kernel CSR build (1 CTA per graph) -----------------
__global__ void __launch_bounds__(256)
csr_build(const int* __restrict__ ei) {
    __shared__ int cnt[NPG];
    __shared__ int sh[256];
    const int g = blockIdx.x, tid = threadIdx.x;
    const int ebase = g * EPG, nbase = g * NPG;
    cnt[tid] = 0; cnt[tid + 256] = 0;
    __syncthreads();
#pragma unroll
    for (int i = tid; i < EPG; i += 256)
        atomicAdd(&cnt[ei[EE + ebase + i] - nbase], 1);
    __syncthreads();
    const int c0 = cnt[2 * tid], c1 = cnt[2 * tid + 1];
    const int tot = c0 + c1;
    sh[tid] = tot;
    __syncthreads();
    for (int s = 1; s < 256; s <<= 1) {
        const int v = (tid >= s) ? sh[tid - s] : 0;
        __syncthreads();
        sh[tid] += v;
        __syncthreads();
    }
    const int base = sh[tid] - tot;
    g_off[nbase + 2 * tid]     = ebase + base;
    g_off[nbase + 2 * tid + 1] = ebase + base + c0;
    cnt[2 * tid] = base;
    cnt[2 * tid + 1] = base + c0;
    if (g == BB - 1 && tid == 0) g_off[NN] = EE;
    __syncthreads();
#pragma unroll
    for (int i = tid; i < EPG; i += 256) {
        const int d = ei[EE + ebase + i] - nbase;
        const int p = atomicAdd(&cnt[d], 1);
        g_csrc[ebase + p] = ei[ebase + i];
    }
}

// ---------------- attention logits: es/ed per (node, head) -----------------
__global__ void esed_kernel(const float* __restrict__ hlin,
                            const float* __restrict__ a_src,
                            const float* __restrict__ a_dst,
                            float* __restrict__ es, float* __restrict__ ed) {
    const int w = (blockIdx.x * blockDim.x + threadIdx.x) >> 5;
    const int lane = threadIdx.x & 31;
    if (w >= NN * HH) return;
    const int n = w >> 2, h = w & 3;
    const float* hp = hlin + (size_t)n * CC + h * FH;
    const float v0 = hp[lane], v1 = hp[lane + 32];
    float s = v0 * a_src[h * FH + lane] + v1 * a_src[h * FH + lane + 32];
    float d = v0 * a_dst[h * FH + lane] + v1 * a_dst[h * FH + lane + 32];
#pragma unroll
    for (int o = 16; o; o >>= 1) {
        s += __shfl_xor_sync(0xffffffffu, s, o);
        d += __shfl_xor_sync(0xffffffffu, d, o);
    }
    if (lane == 0) { es[w] = s; ed[w] = d; }
}

// ---------------- fused softmax + aggregate + bias + ELU --------------------
// If out_hi != nullptr, writes tf32 hi/lo split pair (input for next GEMM);
// otherwise writes fp32 to out_f32.
__global__ void __launch_bounds__(256)
gat_fused(const int* __restrict__ off, const int* __restrict__ csrc,
          const float* __restrict__ es, const float* __restrict__ ed,
          const float* __restrict__ hlin, const float* __restrict__ bias,
          float* __restrict__ out_f32, float* __restrict__ out_hi,
          float* __restrict__ out_lo) {
    const int n = (blockIdx.x * blockDim.x + threadIdx.x) >> 5;
    const int lane = threadIdx.x & 31;
    if (n >= NN) return;

    const float4 edv = ((const float4*)ed)[n];
    const float4 esv = ((const float4*)es)[n];
    const float xs0 = __expf(leaky(esv.x + edv.x));
    const float xs1 = __expf(leaky(esv.y + edv.y));
    const float xs2 = __expf(leaky(esv.z + edv.z));
    const float xs3 = __expf(leaky(esv.w + edv.w));

    const int hi = lane >> 4;
    const float4* hn = (const float4*)(hlin + (size_t)n * CC);
    float4 acc0 = hn[lane];
    float4 acc1 = hn[32 + lane];
    const float sa0 = hi ? xs1 : xs0;
    const float sa1 = hi ? xs3 : xs2;
    acc0.x *= sa0; acc0.y *= sa0; acc0.z *= sa0; acc0.w *= sa0;
    acc1.x *= sa1; acc1.y *= sa1; acc1.z *= sa1; acc1.w *= sa1;

    float ts0 = 0.f, ts1 = 0.f, ts2 = 0.f, ts3 = 0.f;
    const int o0 = off[n], o1 = off[n + 1];
    for (int base = o0; base < o1; base += 32) {
        const int cnt = min(32, o1 - base);
        int s = 0;
        float t0 = 0.f, t1 = 0.f, t2 = 0.f, t3 = 0.f;
        if (lane < cnt) {
            s = csrc[base + lane];
            const float4 ess = ((const float4*)es)[s];
            t0 = __expf(leaky(ess.x + edv.x));
            t1 = __expf(leaky(ess.y + edv.y));
            t2 = __expf(leaky(ess.z + edv.z));
            t3 = __expf(leaky(ess.w + edv.w));
        }
        ts0 += t0; ts1 += t1; ts2 += t2; ts3 += t3;

        int se = __shfl_sync(0xffffffffu, s, 0);
        const float4* hs = (const float4*)(hlin + (size_t)se * CC);
        float4 v0n = hs[lane], v1n = hs[32 + lane];
        for (int e = 0; e < cnt; e++) {
            const float4 v0 = v0n, v1 = v1n;
            const float w0 = __shfl_sync(0xffffffffu, t0, e);
            const float w1 = __shfl_sync(0xffffffffu, t1, e);
            const float w2 = __shfl_sync(0xffffffffu, t2, e);
            const float w3 = __shfl_sync(0xffffffffu, t3, e);
            if (e + 1 < cnt) {
                se = __shfl_sync(0xffffffffu, s, e + 1);
                const float4* hsn = (const float4*)(hlin + (size_t)se * CC);
                v0n = hsn[lane]; v1n = hsn[32 + lane];
            }
            const float aw0 = hi ? w1 : w0;
            const float aw1 = hi ? w3 : w2;
            acc0.x += aw0 * v0.x; acc0.y += aw0 * v0.y;
            acc0.z += aw0 * v0.z; acc0.w += aw0 * v0.w;
            acc1.x += aw1 * v1.x; acc1.y += aw1 * v1.y;
            acc1.z += aw1 * v1.z; acc1.w += aw1 * v1.w;
        }
    }
#pragma unroll
    for (int o = 16; o; o >>= 1) {
        ts0 += __shfl_xor_sync(0xffffffffu, ts0, o);
        ts1 += __shfl_xor_sync(0xffffffffu, ts1, o);
        ts2 += __shfl_xor_sync(0xffffffffu, ts2, o);
        ts3 += __shfl_xor_sync(0xffffffffu, ts3, o);
    }
    const float di0 = 1.f / (xs0 + ts0 + 1e-16f);
    const float di1 = 1.f / (xs1 + ts1 + 1e-16f);
    const float di2 = 1.f / (xs2 + ts2 + 1e-16f);
    const float di3 = 1.f / (xs3 + ts3 + 1e-16f);
    const float d0 = hi ? di1 : di0;
    const float d1 = hi ? di3 : di2;

    const float4 bv0 = ((const float4*)bias)[lane];
    const float4 bv1 = ((const float4*)bias)[32 + lane];
    float4 o0v, o1v;
    o0v.x = acc0.x * d0 + bv0.x; o0v.y = acc0.y * d0 + bv0.y;
    o0v.z = acc0.z * d0 + bv0.z; o0v.w = acc0.w * d0 + bv0.w;
    o1v.x = acc1.x * d1 + bv1.x; o1v.y = acc1.y * d1 + bv1.y;
    o1v.z = acc1.z * d1 + bv1.z; o1v.w = acc1.w * d1 + bv1.w;
    o0v.x = o0v.x > 0.f ? o0v.x : (__expf(o0v.x) - 1.f);
    o0v.y = o0v.y > 0.f ? o0v.y : (__expf(o0v.y) - 1.f);
    o0v.z = o0v.z > 0.f ? o0v.z : (__expf(o0v.z) - 1.f);
    o0v.w = o0v.w > 0.f ? o0v.w : (__expf(o0v.w) - 1.f);
    o1v.x = o1v.x > 0.f ? o1v.x : (__expf(o1v.x) - 1.f);
    o1v.y = o1v.y > 0.f ? o1v.y : (__expf(o1v.y) - 1.f);
    o1v.z = o1v.z > 0.f ? o1v.z : (__expf(o1v.z) - 1.f);
    o1v.w = o1v.w > 0.f ? o1v.w : (__expf(o1v.w) - 1.f);
    if (out_hi) {
        float4 h0, l0, h1, l1;
        split4(o0v, h0, l0);
        split4(o1v, h1, l1);
        ((float4*)out_hi)[(size_t)n * 64 + lane]      = h0;
        ((float4*)out_lo)[(size_t)n * 64 + lane]      = l0;
        ((float4*)out_hi)[(size_t)n * 64 + 32 + lane] = h1;
        ((float4*)out_lo)[(size_t)n * 64 + 32 + lane] = l1;
    } else {
        ((float4*)out_f32)[(size_t)n * 64 + lane]      = o0v;
        ((float4*)out_f32)[(size_t)n * 64 + 32 + lane] = o1v;
    }
}

// ---------------- fused pooling: score + top-k + gather (split output) ------
template <int NPB, int KSEL>
__global__ void pool_fused(const float* __restrict__ X, const float* __restrict__ sw,
                           float* __restrict__ selh, float* __restrict__ sell) {
    __shared__ float sv[NPB];
    __shared__ int si[NPB];
    const int b = blockIdx.x, t = threadIdx.x;
    const int wid = t >> 5, lane = t & 31;

#pragma unroll
    for (int rr = 0; rr < 32; rr++) {
        const int local = wid * 32 + rr;
        const float* xp = X + (size_t)(b * NPB + local) * CC;
        float s = 0.f;
#pragma unroll
        for (int c = 0; c < CC / 32; c++) s += xp[lane + c * 32] * sw[lane + c * 32];
#pragma unroll
        for (int o = 16; o; o >>= 1) s += __shfl_xor_sync(0xffffffffu, s, o);
        if (lane == 0) { sv[local] = s; si[local] = local; }
    }
    __syncthreads();

    for (int k = 2; k <= NPB; k <<= 1) {
        for (int j = k >> 1; j > 0; j >>= 1) {
            const int ixj = t ^ j;
            if (ixj > t) {
                const bool desc = ((t & k) == 0);
                const float a = sv[t], c = sv[ixj];
                if ((a < c) == desc) {
                    sv[t] = c; sv[ixj] = a;
                    const int tmp = si[t]; si[t] = si[ixj]; si[ixj] = tmp;
                }
            }
            __syncthreads();
        }
    }

    for (int idx = t; idx < KSEL * 64; idx += NPB) {
        const int r = idx >> 6, q = idx & 63;
        const int src = b * NPB + si[r];
        const float4 v = ((const float4*)X)[(size_t)src * 64 + q];
        float4 h, l;
        split4(v, h, l);
        ((float4*)selh)[(size_t)(b * KSEL + r) * 64 + q] = h;
        ((float4*)sell)[(size_t)(b * KSEL + r) * 64 + q] = l;
    }
}

// ---------------- fused readout: mean + fc1(relu) + fc2 + log_softmax -------
__global__ void __launch_bounds__(256)
readout_fused(const float* __restrict__ X, const float* __restrict__ c1w,
              const float* __restrict__ c1b, const float* __restrict__ c2w,
              const float* __restrict__ c2b, float* __restrict__ out) {
    __shared__ float gm[CC];
    __shared__ float f1[64];
    const int b = blockIdx.x, t = threadIdx.x;
    const int wid = t >> 5, lane = t & 31;

    float s = 0.f;
    const float* xp = X + (size_t)b * K2 * CC + t;
#pragma unroll 4
    for (int r = 0; r < K2; r++) s += xp[r * CC];
    gm[t] = s * (1.f / K2);
    __syncthreads();

#pragma unroll
    for (int oo = 0; oo < 8; oo++) {
        const int o = wid * 8 + oo;
        float acc = 0.f;
#pragma unroll
        for (int c = 0; c < CC / 32; c++)
            acc += gm[lane + c * 32] * c1w[(lane + c * 32) * 64 + o];
#pragma unroll
        for (int off = 16; off; off >>= 1) acc += __shfl_xor_sync(0xffffffffu, acc, off);
        if (lane == 0) {
            const float v = acc + c1b[o];
            f1[o] = v > 0.f ? v : 0.f;
        }
    }
    __syncthreads();

    if (wid == 0) {
        float l0 = 0.f, l1 = 0.f;
#pragma unroll
        for (int k = lane; k < 64; k += 32) {
            const float v = f1[k];
            l0 += v * c2w[k * 2 + 0];
            l1 += v * c2w[k * 2 + 1];
        }
#pragma unroll
        for (int off = 16; off; off >>= 1) {
            l0 += __shfl_xor_sync(0xffffffffu, l0, off);
            l1 += __shfl_xor_sync(0xffffffffu, l1, off);
        }
        if (lane == 0) {
            l0 += c2b[0]; l1 += c2b[1];
            const float mm = fmaxf(l0, l1);
            const float lse = mm + logf(__expf(l0 - mm) + __expf(l1 - mm));
            out[b * 2 + 0] = l0 - lse;
            out[b * 2 + 1] = l1 - lse;
        }
    }
}

// ---------------- host orchestration ----------------------------------------
static float* sym(const void* s) {
    void* p = nullptr;
    cudaGetSymbolAddress(&p, (const void*)s);
    return (float*)p;
}

extern "C" void kernel_launch(void* const* d_in, const int* in_sizes, int n_in,
                              void* d_out, int out_size) {
    const float* x      = (const float*)d_in[0];
    const int*   ei     = (const int*)  d_in[1];
    const float* W1     = (const float*)d_in[3];
    const float* asrc1  = (const float*)d_in[4];
    const float* adst1  = (const float*)d_in[5];
    const float* b1     = (const float*)d_in[6];
    const float* W2     = (const float*)d_in[7];
    const float* asrc2  = (const float*)d_in[8];
    const float* adst2  = (const float*)d_in[9];
    const float* b2     = (const float*)d_in[10];
    const float* p1_sw  = (const float*)d_in[11];
    const float* p1_tw  = (const float*)d_in[13];
    const float* p1_tb  = (const float*)d_in[14];
    const float* p2_sw  = (const float*)d_in[15];
    const float* p2_tw  = (const float*)d_in[17];
    const float* p2_tb  = (const float*)d_in[18];
    const float* c1w    = (const float*)d_in[19];
    const float* c1b    = (const float*)d_in[20];
    const float* c2w    = (const float*)d_in[21];
    const float* c2b    = (const float*)d_in[22];
    float* out = (float*)d_out;

    float* hlin  = sym(g_hlin);
    float* hout  = sym(g_hout);
    float* es    = sym(g_es);
    float* ed    = sym(g_ed);
    int*   off   = (int*)sym(g_off);
    int*   csrc  = (int*)sym(g_csrc);
    float* pool1 = sym(g_pool1);
    float* pool2 = sym(g_pool2);
    float* xh = sym(g_xh),   *xl = sym(g_xl);
    float* hh = sym(g_hh),   *hl = sym(g_hl);
    float* selh = sym(g_selh), *sell = sym(g_sell);
    float* w1h = sym(g_w1h), *w1l = sym(g_w1l);
    float* w2h = sym(g_w2h), *w2l = sym(g_w2l);
    float* p1h = sym(g_p1h), *p1l = sym(g_p1l);
    float* p2h = sym(g_p2h), *p2l = sym(g_p2l);

    dim3 t256(256);

    // ---- CSR build + operand splits ----
    csr_build<<<BB, t256>>>(ei);
    split_kernel<<<(NN * FIN / 4) / 256, t256>>>(x, xh, xl, NN * FIN / 4);
    split_kernel<<<(FIN * CC / 4) / 256, t256>>>(W1, w1h, w1l, FIN * CC / 4);
    split_kernel<<<(CC * CC / 4) / 256, t256>>>(W2, w2h, w2l, CC * CC / 4);
    split_kernel<<<(CC * CC / 4) / 256, t256>>>(p1_tw, p1h, p1l, CC * CC / 4);
    split_kernel<<<(CC * CC / 4) / 256, t256>>>(p2_tw, p2h, p2l, CC * CC / 4);

    // ---- GAT layer 1 ----
    tf32_gemm<<<dim3(CC / 128, NN / 128), t256>>>(xh, xl, w1h, w1l, nullptr, hlin,
                                                  NN, CC, FIN);
    esed_kernel<<<(NN * HH) / 8, t256>>>(hlin, asrc1, adst1, es, ed);
    gat_fused<<<(NN * 32) / 256, t256>>>(off, csrc, es, ed, hlin, b1,
                                         nullptr, hh, hl);

    // ---- GAT layer 2 ----
    tf32_gemm<<<dim3(CC / 128, NN / 128), t256>>>(hh, hl, w2h, w2l, nullptr, hlin,
                                                  NN, CC, CC);
    esed_kernel<<<(NN * HH) / 8, t256>>>(hlin, asrc2, adst2, es, ed);
    gat_fused<<<(NN * 32) / 256, t256>>>(off, csrc, es, ed, hlin, b2,
                                         hout, nullptr, nullptr);

    // ---- Pool 1 (top-256 of 512 per graph) ----
    pool_fused<NPG, K1><<<BB, NPG>>>(hout, p1_sw, selh, sell);
    tf32_gemm<<<dim3(CC / 128, (BB * K1) / 128), t256>>>(selh, sell, p1h, p1l,
                                                         p1_tb, pool1, BB * K1, CC, CC);

    // ---- Pool 2 (top-128 of 256 per graph) ----
    pool_fused<K1, K2><<<BB, K1>>>(pool1, p2_sw, selh, sell);
    tf32_gemm<<<dim3(CC / 128, (BB * K2) / 128), t256>>>(selh, sell, p2h, p2l,
                                                         p2_tb, pool2, BB * K2, CC, CC);

    // ---- readout ----
    readout_fused<<<BB, t256>>>(pool2, c1w, c1b, c2w, c2b, out);
}

// round 15
// speedup vs baseline: 1.1403x; 1.1403x over previous
#include <cuda_runtime.h>
#include <cuda_bf16.h>
#include <cstdint>

// Problem constants
#define NN   32768
#define FIN  128
#define CC   256
#define HH   4
#define FH   64
#define EE   524288
#define BB   64
#define NPG  512
#define EPG  (EE / BB)
#define K1   256
#define K2   128

// ---------------- scratch (device globals; no allocation allowed) ----------
__device__ float    g_hlin[NN * CC];
__device__ float    g_hout[NN * CC];
__device__ float    g_es[NN * HH];
__device__ float    g_ed[NN * HH];
__device__ int      g_off[NN + 1];
__device__ int      g_csrc[EE];
__device__ float    g_sel[(BB * K1) * CC];
__device__ float    g_pool1[(BB * K1) * CC];
__device__ float    g_pool2[(BB * K2) * CC];
// pre-split tf32 weight buffers (hi/lo)
__device__ float    g_w1h[FIN * CC];
__device__ float    g_w1l[FIN * CC];
__device__ float    g_w2h[CC * CC];
__device__ float    g_w2l[CC * CC];
__device__ float    g_p1h[CC * CC];
__device__ float    g_p1l[CC * CC];
__device__ float    g_p2h[CC * CC];
__device__ float    g_p2l[CC * CC];

__device__ __forceinline__ float leaky(float x) { return x > 0.f ? x : 0.2f * x; }

// ---------------- tf32 helpers ----------------------------------------------
__device__ __forceinline__ float tf32r(float x) {
    uint32_t u;
    asm("cvt.rna.tf32.f32 %0, %1;" : "=r"(u) : "f"(x));
    return __uint_as_float(u);
}
__device__ __forceinline__ void split4(const float4 v, float4& h, float4& l) {
    h.x = tf32r(v.x); l.x = v.x - h.x;
    h.y = tf32r(v.y); l.y = v.y - h.y;
    h.z = tf32r(v.z); l.z = v.z - h.z;
    h.w = tf32r(v.w); l.w = v.w - h.w;
}
__device__ __forceinline__ void mma8(float4& d, const uint32_t* a, const uint32_t* b) {
    asm volatile("mma.sync.aligned.m16n8k8.row.col.f32.tf32.tf32.f32 "
        "{%0,%1,%2,%3}, {%4,%5,%6,%7}, {%8,%9}, {%0,%1,%2,%3};"
        : "+f"(d.x), "+f"(d.y), "+f"(d.z), "+f"(d.w)
        : "r"(a[0]), "r"(a[1]), "r"(a[2]), "r"(a[3]), "r"(b[0]), "r"(b[1]));
}

// ---------------- weight split kernel ----------------------------------------
__global__ void split_kernel(const float* __restrict__ src, float* __restrict__ hi,
                             float* __restrict__ lo, int n4) {
    const int i = blockIdx.x * blockDim.x + threadIdx.x;
    if (i >= n4) return;
    float4 h, l;
    split4(((const float4*)src)[i], h, l);
    ((float4*)hi)[i] = h;
    ((float4*)lo)[i] = l;
}

// ---------------- 3xTF32 GEMM: A split in-kernel, B (weights) pre-split ------
// C[M,N]=A@B (+bias). 128x128 CTA tile, 256 threads (2x4 warps of 64x32),
// BK=16. Optional fused es/ed epilogue (GAT layer GEMMs, N==256, bias null).
#define ASTR 20
#define BSTR 136
__global__ void __launch_bounds__(256)
tf32_gemm(const float* __restrict__ A,
          const float* __restrict__ Bh, const float* __restrict__ Bl,
          const float* __restrict__ bias, float* __restrict__ Cm,
          int M, int N, int K,
          const float* __restrict__ a_src, const float* __restrict__ a_dst,
          float* __restrict__ es, float* __restrict__ ed) {
    __shared__ float As_hi[128 * ASTR];
    __shared__ float As_lo[128 * ASTR];
    __shared__ float Bs_hi[16 * BSTR];
    __shared__ float Bs_lo[16 * BSTR];

    const int tid = threadIdx.x;
    const int lane = tid & 31, wid = tid >> 5;
    const int warp_m = wid & 1, warp_n = wid >> 1;
    const int g = lane >> 2, t = lane & 3;
    const int wm0 = warp_m * 64, wn0 = warp_n * 32;
    const int row0 = blockIdx.y * 128;
    const int col0 = blockIdx.x * 128;

    const int arow0 = tid >> 2, ac0 = (tid & 3) << 2;
    const int arow1 = arow0 + 64;
    const int brow0 = tid >> 5, bc0 = (tid & 31) << 2;
    const int brow1 = brow0 + 8;

    float4 acc[4][4];
#pragma unroll
    for (int i = 0; i < 4; i++)
#pragma unroll
        for (int j = 0; j < 4; j++) acc[i][j] = make_float4(0.f, 0.f, 0.f, 0.f);

    const int ntiles = K >> 4;
    float4 pa0, pa1, pbh0, pbh1, pbl0, pbl1;
    pa0 = *(const float4*)&A[(size_t)(row0 + arow0) * K + ac0];
    pa1 = *(const float4*)&A[(size_t)(row0 + arow1) * K + ac0];
    pbh0 = *(const float4*)&Bh[(size_t)brow0 * N + col0 + bc0];
    pbh1 = *(const float4*)&Bh[(size_t)brow1 * N + col0 + bc0];
    pbl0 = *(const float4*)&Bl[(size_t)brow0 * N + col0 + bc0];
    pbl1 = *(const float4*)&Bl[(size_t)brow1 * N + col0 + bc0];

    for (int kt = 0; kt < ntiles; kt++) {
        {
            float4 h, l;
            split4(pa0, h, l);
            *(float4*)&As_hi[arow0 * ASTR + ac0] = h;
            *(float4*)&As_lo[arow0 * ASTR + ac0] = l;
            split4(pa1, h, l);
            *(float4*)&As_hi[arow1 * ASTR + ac0] = h;
            *(float4*)&As_lo[arow1 * ASTR + ac0] = l;
        }
        *(float4*)&Bs_hi[brow0 * BSTR + bc0] = pbh0;
        *(float4*)&Bs_hi[brow1 * BSTR + bc0] = pbh1;
        *(float4*)&Bs_lo[brow0 * BSTR + bc0] = pbl0;
        *(float4*)&Bs_lo[brow1 * BSTR + bc0] = pbl1;
        __syncthreads();
        if (kt + 1 < ntiles) {
            const int k0 = (kt + 1) << 4;
            pa0 = *(const float4*)&A[(size_t)(row0 + arow0) * K + k0 + ac0];
            pa1 = *(const float4*)&A[(size_t)(row0 + arow1) * K + k0 + ac0];
            pbh0 = *(const float4*)&Bh[(size_t)(k0 + brow0) * N + col0 + bc0];
            pbh1 = *(const float4*)&Bh[(size_t)(k0 + brow1) * N + col0 + bc0];
            pbl0 = *(const float4*)&Bl[(size_t)(k0 + brow0) * N + col0 + bc0];
            pbl1 = *(const float4*)&Bl[(size_t)(k0 + brow1) * N + col0 + bc0];
        }
        const uint32_t* AhS = (const uint32_t*)As_hi;
        const uint32_t* AlS = (const uint32_t*)As_lo;
        const uint32_t* BhS = (const uint32_t*)Bs_hi;
        const uint32_t* BlS = (const uint32_t*)Bs_lo;
#pragma unroll
        for (int k8 = 0; k8 < 16; k8 += 8) {
            uint32_t af[4][4], bh[4][2], bl[4][2];
#pragma unroll
            for (int nt = 0; nt < 4; nt++) {
                const int c = wn0 + nt * 8 + g;
                bh[nt][0] = BhS[(k8 + t) * BSTR + c];
                bh[nt][1] = BhS[(k8 + t + 4) * BSTR + c];
                bl[nt][0] = BlS[(k8 + t) * BSTR + c];
                bl[nt][1] = BlS[(k8 + t + 4) * BSTR + c];
            }
#pragma unroll
            for (int mt = 0; mt < 4; mt++) {
                const int r = wm0 + mt * 16 + g;
                af[mt][0] = AhS[r * ASTR + k8 + t];
                af[mt][1] = AhS[(r + 8) * ASTR + k8 + t];
                af[mt][2] = AhS[r * ASTR + k8 + t + 4];
                af[mt][3] = AhS[(r + 8) * ASTR + k8 + t + 4];
            }
#pragma unroll
            for (int mt = 0; mt < 4; mt++)
#pragma unroll
                for (int nt = 0; nt < 4; nt++) {
                    mma8(acc[mt][nt], af[mt], bh[nt]);
                    mma8(acc[mt][nt], af[mt], bl[nt]);
                }
#pragma unroll
            for (int mt = 0; mt < 4; mt++) {
                const int r = wm0 + mt * 16 + g;
                af[mt][0] = AlS[r * ASTR + k8 + t];
                af[mt][1] = AlS[(r + 8) * ASTR + k8 + t];
                af[mt][2] = AlS[r * ASTR + k8 + t + 4];
                af[mt][3] = AlS[(r + 8) * ASTR + k8 + t + 4];
            }
#pragma unroll
            for (int mt = 0; mt < 4; mt++)
#pragma unroll
                for (int nt = 0; nt < 4; nt++)
                    mma8(acc[mt][nt], af[mt], bh[nt]);
        }
        __syncthreads();
    }

    // store C (+bias)
#pragma unroll
    for (int nt = 0; nt < 4; nt++) {
        const int c = col0 + wn0 + nt * 8 + 2 * t;
        float2 bv = make_float2(0.f, 0.f);
        if (bias) bv = *(const float2*)&bias[c];
#pragma unroll
        for (int mt = 0; mt < 4; mt++) {
            const int r = row0 + wm0 + mt * 16 + g;
            float2 lo2 = make_float2(acc[mt][nt].x + bv.x, acc[mt][nt].y + bv.y);
            float2 hi2 = make_float2(acc[mt][nt].z + bv.x, acc[mt][nt].w + bv.y);
            *(float2*)&Cm[(size_t)r * N + c] = lo2;
            *(float2*)&Cm[(size_t)(r + 8) * N + c] = hi2;
        }
    }

    // ---- fused es/ed epilogue (GAT layer GEMMs only) ----
    if (a_src) {
        float* es_s = As_hi;          // [128][2] (row-local, head-local)
        float* ed_s = As_hi + 256;
        for (int i = tid; i < 512; i += 256) As_hi[i] = 0.f;
        __syncthreads();
        const int lh = wn0 >> 6;      // this warp's local head (0 or 1)
        float asv[4][2], adv[4][2];
#pragma unroll
        for (int nt = 0; nt < 4; nt++) {
            const int gc = col0 + wn0 + nt * 8 + 2 * t;   // global col = h*64+f
            asv[nt][0] = a_src[gc];     asv[nt][1] = a_src[gc + 1];
            adv[nt][0] = a_dst[gc];     adv[nt][1] = a_dst[gc + 1];
        }
#pragma unroll
        for (int mt = 0; mt < 4; mt++) {
            float se1 = 0.f, de1 = 0.f, se2 = 0.f, de2 = 0.f;
#pragma unroll
            for (int nt = 0; nt < 4; nt++) {
                se1 += acc[mt][nt].x * asv[nt][0] + acc[mt][nt].y * asv[nt][1];
                de1 += acc[mt][nt].x * adv[nt][0] + acc[mt][nt].y * adv[nt][1];
                se2 += acc[mt][nt].z * asv[nt][0] + acc[mt][nt].w * asv[nt][1];
                de2 += acc[mt][nt].z * adv[nt][0] + acc[mt][nt].w * adv[nt][1];
            }
            // reduce over t (lane bits 0-1)
#pragma unroll
            for (int m = 1; m < 4; m <<= 1) {
                se1 += __shfl_xor_sync(0xffffffffu, se1, m);
                de1 += __shfl_xor_sync(0xffffffffu, de1, m);
                se2 += __shfl_xor_sync(0xffffffffu, se2, m);
                de2 += __shfl_xor_sync(0xffffffffu, de2, m);
            }
            if (t == 0) {
                const int r1 = wm0 + mt * 16 + g;
                atomicAdd(&es_s[r1 * 2 + lh], se1);
                atomicAdd(&ed_s[r1 * 2 + lh], de1);
                atomicAdd(&es_s[(r1 + 8) * 2 + lh], se2);
                atomicAdd(&ed_s[(r1 + 8) * 2 + lh], de2);
            }
        }
        __syncthreads();
        const int r = tid >> 1, l = tid & 1;
        const int h0 = col0 >> 6;
        es[(size_t)(row0 + r) * HH + h0 + l] = es_s[r * 2 + l];
        ed[(size_t)(row0 + r) * HH + h0 + l] = ed_s[r * 2 + l];
    }
}

// ---------------- single-kernel CSR build (1 CTA per graph) -----------------
__global__ void __launch_bounds__(256)
csr_build(const int* __restrict__ ei) {
    __shared__ int cnt[NPG];
    __shared__ int sh[256];
    const int g = blockIdx.x, tid = threadIdx.x;
    const int ebase = g * EPG, nbase = g * NPG;
    cnt[tid] = 0; cnt[tid + 256] = 0;
    __syncthreads();
#pragma unroll
    for (int i = tid; i < EPG; i += 256)
        atomicAdd(&cnt[ei[EE + ebase + i] - nbase], 1);
    __syncthreads();
    const int c0 = cnt[2 * tid], c1 = cnt[2 * tid + 1];
    const int tot = c0 + c1;
    sh[tid] = tot;
    __syncthreads();
    for (int s = 1; s < 256; s <<= 1) {
        const int v = (tid >= s) ? sh[tid - s] : 0;
        __syncthreads();
        sh[tid] += v;
        __syncthreads();
    }
    const int base = sh[tid] - tot;
    g_off[nbase + 2 * tid]     = ebase + base;
    g_off[nbase + 2 * tid + 1] = ebase + base + c0;
    cnt[2 * tid] = base;
    cnt[2 * tid + 1] = base + c0;
    if (g == BB - 1 && tid == 0) g_off[NN] = EE;
    __syncthreads();
#pragma unroll
    for (int i = tid; i < EPG; i += 256) {
        const int d = ei[EE + ebase + i] - nbase;
        const int p = atomicAdd(&cnt[d], 1);
        g_csrc[ebase + p] = ei[ebase + i];
    }
}

// ---------------- fused softmax + aggregate + bias + ELU (R10-proven) -------
__global__ void __launch_bounds__(256)
gat_fused(const int* __restrict__ off, const int* __restrict__ csrc,
          const float* __restrict__ es, const float* __restrict__ ed,
          const float* __restrict__ hlin, const float* __restrict__ bias,
          float* __restrict__ out) {
    const int n = (blockIdx.x * blockDim.x + threadIdx.x) >> 5;
    const int lane = threadIdx.x & 31;
    if (n >= NN) return;

    const float4 edv = ((const float4*)ed)[n];
    const float4 esv = ((const float4*)es)[n];
    const float xs0 = __expf(leaky(esv.x + edv.x));
    const float xs1 = __expf(leaky(esv.y + edv.y));
    const float xs2 = __expf(leaky(esv.z + edv.z));
    const float xs3 = __expf(leaky(esv.w + edv.w));

    const int hi = lane >> 4;
    const float4* hn = (const float4*)(hlin + (size_t)n * CC);
    float4 acc0 = hn[lane];
    float4 acc1 = hn[32 + lane];
    const float sa0 = hi ? xs1 : xs0;
    const float sa1 = hi ? xs3 : xs2;
    acc0.x *= sa0; acc0.y *= sa0; acc0.z *= sa0; acc0.w *= sa0;
    acc1.x *= sa1; acc1.y *= sa1; acc1.z *= sa1; acc1.w *= sa1;

    float ts0 = 0.f, ts1 = 0.f, ts2 = 0.f, ts3 = 0.f;
    const int o0 = off[n], o1 = off[n + 1];
    for (int base = o0; base < o1; base += 32) {
        const int cnt = min(32, o1 - base);
        int s = 0;
        float t0 = 0.f, t1 = 0.f, t2 = 0.f, t3 = 0.f;
        if (lane < cnt) {
            s = csrc[base + lane];
            const float4 ess = ((const float4*)es)[s];
            t0 = __expf(leaky(ess.x + edv.x));
            t1 = __expf(leaky(ess.y + edv.y));
            t2 = __expf(leaky(ess.z + edv.z));
            t3 = __expf(leaky(ess.w + edv.w));
        }
        ts0 += t0; ts1 += t1; ts2 += t2; ts3 += t3;

        int se = __shfl_sync(0xffffffffu, s, 0);
        const float4* hs = (const float4*)(hlin + (size_t)se * CC);
        float4 v0n = hs[lane], v1n = hs[32 + lane];
        for (int e = 0; e < cnt; e++) {
            const float4 v0 = v0n, v1 = v1n;
            const float w0 = __shfl_sync(0xffffffffu, t0, e);
            const float w1 = __shfl_sync(0xffffffffu, t1, e);
            const float w2 = __shfl_sync(0xffffffffu, t2, e);
            const float w3 = __shfl_sync(0xffffffffu, t3, e);
            if (e + 1 < cnt) {
                se = __shfl_sync(0xffffffffu, s, e + 1);
                const float4* hsn = (const float4*)(hlin + (size_t)se * CC);
                v0n = hsn[lane]; v1n = hsn[32 + lane];
            }
            const float aw0 = hi ? w1 : w0;
            const float aw1 = hi ? w3 : w2;
            acc0.x += aw0 * v0.x; acc0.y += aw0 * v0.y;
            acc0.z += aw0 * v0.z; acc0.w += aw0 * v0.w;
            acc1.x += aw1 * v1.x; acc1.y += aw1 * v1.y;
            acc1.z += aw1 * v1.z; acc1.w += aw1 * v1.w;
        }
    }
#pragma unroll
    for (int o = 16; o; o >>= 1) {
        ts0 += __shfl_xor_sync(0xffffffffu, ts0, o);
        ts1 += __shfl_xor_sync(0xffffffffu, ts1, o);
        ts2 += __shfl_xor_sync(0xffffffffu, ts2, o);
        ts3 += __shfl_xor_sync(0xffffffffu, ts3, o);
    }
    const float di0 = 1.f / (xs0 + ts0 + 1e-16f);
    const float di1 = 1.f / (xs1 + ts1 + 1e-16f);
    const float di2 = 1.f / (xs2 + ts2 + 1e-16f);
    const float di3 = 1.f / (xs3 + ts3 + 1e-16f);
    const float d0 = hi ? di1 : di0;
    const float d1 = hi ? di3 : di2;

    const float4 bv0 = ((const float4*)bias)[lane];
    const float4 bv1 = ((const float4*)bias)[32 + lane];
    float4 o0v, o1v;
    o0v.x = acc0.x * d0 + bv0.x; o0v.y = acc0.y * d0 + bv0.y;
    o0v.z = acc0.z * d0 + bv0.z; o0v.w = acc0.w * d0 + bv0.w;
    o1v.x = acc1.x * d1 + bv1.x; o1v.y = acc1.y * d1 + bv1.y;
    o1v.z = acc1.z * d1 + bv1.z; o1v.w = acc1.w * d1 + bv1.w;
    o0v.x = o0v.x > 0.f ? o0v.x : (__expf(o0v.x) - 1.f);
    o0v.y = o0v.y > 0.f ? o0v.y : (__expf(o0v.y) - 1.f);
    o0v.z = o0v.z > 0.f ? o0v.z : (__expf(o0v.z) - 1.f);
    o0v.w = o0v.w > 0.f ? o0v.w : (__expf(o0v.w) - 1.f);
    o1v.x = o1v.x > 0.f ? o1v.x : (__expf(o1v.x) - 1.f);
    o1v.y = o1v.y > 0.f ? o1v.y : (__expf(o1v.y) - 1.f);
    o1v.z = o1v.z > 0.f ? o1v.z : (__expf(o1v.z) - 1.f);
    o1v.w = o1v.w > 0.f ? o1v.w : (__expf(o1v.w) - 1.f);
    ((float4*)out)[(size_t)n * 64 + lane]      = o0v;
    ((float4*)out)[(size_t)n * 64 + 32 + lane] = o1v;
}

// ---------------- fused pooling: score + top-k + gather ---------------------
template <int NPB, int KSEL>
__global__ void pool_fused(const float* __restrict__ X, const float* __restrict__ sw,
                           float* __restrict__ selb) {
    __shared__ float sv[NPB];
    __shared__ int si[NPB];
    const int b = blockIdx.x, t = threadIdx.x;
    const int wid = t >> 5, lane = t & 31;

#pragma unroll
    for (int rr = 0; rr < 32; rr++) {
        const int local = wid * 32 + rr;
        const float* xp = X + (size_t)(b * NPB + local) * CC;
        float s = 0.f;
#pragma unroll
        for (int c = 0; c < CC / 32; c++) s += xp[lane + c * 32] * sw[lane + c * 32];
#pragma unroll
        for (int o = 16; o; o >>= 1) s += __shfl_xor_sync(0xffffffffu, s, o);
        if (lane == 0) { sv[local] = s; si[local] = local; }
    }
    __syncthreads();

    for (int k = 2; k <= NPB; k <<= 1) {
        for (int j = k >> 1; j > 0; j >>= 1) {
            const int ixj = t ^ j;
            if (ixj > t) {
                const bool desc = ((t & k) == 0);
                const float a = sv[t], c = sv[ixj];
                if ((a < c) == desc) {
                    sv[t] = c; sv[ixj] = a;
                    const int tmp = si[t]; si[t] = si[ixj]; si[ixj] = tmp;
                }
            }
            __syncthreads();
        }
    }

    for (int idx = t; idx < KSEL * 64; idx += NPB) {
        const int r = idx >> 6, q = idx & 63;
        const int src = b * NPB + si[r];
        ((float4*)selb)[(size_t)(b * KSEL + r) * 64 + q] =
            ((const float4*)X)[(size_t)src * 64 + q];
    }
}

// ---------------- fused readout: mean + fc1(relu) + fc2 + log_softmax -------
__global__ void __launch_bounds__(256)
readout_fused(const float* __restrict__ X, const float* __restrict__ c1w,
              const float* __restrict__ c1b, const float* __restrict__ c2w,
              const float* __restrict__ c2b, float* __restrict__ out) {
    __shared__ float gm[CC];
    __shared__ float f1[64];
    const int b = blockIdx.x, t = threadIdx.x;
    const int wid = t >> 5, lane = t & 31;

    float s = 0.f;
    const float* xp = X + (size_t)b * K2 * CC + t;
#pragma unroll 4
    for (int r = 0; r < K2; r++) s += xp[r * CC];
    gm[t] = s * (1.f / K2);
    __syncthreads();

#pragma unroll
    for (int oo = 0; oo < 8; oo++) {
        const int o = wid * 8 + oo;
        float acc = 0.f;
#pragma unroll
        for (int c = 0; c < CC / 32; c++)
            acc += gm[lane + c * 32] * c1w[(lane + c * 32) * 64 + o];
#pragma unroll
        for (int off = 16; off; off >>= 1) acc += __shfl_xor_sync(0xffffffffu, acc, off);
        if (lane == 0) {
            const float v = acc + c1b[o];
            f1[o] = v > 0.f ? v : 0.f;
        }
    }
    __syncthreads();

    if (wid == 0) {
        float l0 = 0.f, l1 = 0.f;
#pragma unroll
        for (int k = lane; k < 64; k += 32) {
            const float v = f1[k];
            l0 += v * c2w[k * 2 + 0];
            l1 += v * c2w[k * 2 + 1];
        }
#pragma unroll
        for (int off = 16; off; off >>= 1) {
            l0 += __shfl_xor_sync(0xffffffffu, l0, off);
            l1 += __shfl_xor_sync(0xffffffffu, l1, off);
        }
        if (lane == 0) {
            l0 += c2b[0]; l1 += c2b[1];
            const float mm = fmaxf(l0, l1);
            const float lse = mm + logf(__expf(l0 - mm) + __expf(l1 - mm));
            out[b * 2 + 0] = l0 - lse;
            out[b * 2 + 1] = l1 - lse;
        }
    }
}

// ---------------- host orchestration ----------------------------------------
static float* sym(const void* s) {
    void* p = nullptr;
    cudaGetSymbolAddress(&p, (const void*)s);
    return (float*)p;
}

extern "C" void kernel_launch(void* const* d_in, const int* in_sizes, int n_in,
                              void* d_out, int out_size) {
    const float* x      = (const float*)d_in[0];
    const int*   ei     = (const int*)  d_in[1];
    const float* W1     = (const float*)d_in[3];
    const float* asrc1  = (const float*)d_in[4];
    const float* adst1  = (const float*)d_in[5];
    const float* b1     = (const float*)d_in[6];
    const float* W2     = (const float*)d_in[7];
    const float* asrc2  = (const float*)d_in[8];
    const float* adst2  = (const float*)d_in[9];
    const float* b2     = (const float*)d_in[10];
    const float* p1_sw  = (const float*)d_in[11];
    const float* p1_tw  = (const float*)d_in[13];
    const float* p1_tb  = (const float*)d_in[14];
    const float* p2_sw  = (const float*)d_in[15];
    const float* p2_tw  = (const float*)d_in[17];
    const float* p2_tb  = (const float*)d_in[18];
    const float* c1w    = (const float*)d_in[19];
    const float* c1b    = (const float*)d_in[20];
    const float* c2w    = (const float*)d_in[21];
    const float* c2b    = (const float*)d_in[22];
    float* out = (float*)d_out;

    float* hlin  = sym(g_hlin);
    float* hout  = sym(g_hout);
    float* es    = sym(g_es);
    float* ed    = sym(g_ed);
    int*   off   = (int*)sym(g_off);
    int*   csrc  = (int*)sym(g_csrc);
    float* selb  = sym(g_sel);
    float* pool1 = sym(g_pool1);
    float* pool2 = sym(g_pool2);
    float* w1h = sym(g_w1h), *w1l = sym(g_w1l);
    float* w2h = sym(g_w2h), *w2l = sym(g_w2l);
    float* p1h = sym(g_p1h), *p1l = sym(g_p1l);
    float* p2h = sym(g_p2h), *p2l = sym(g_p2l);

    dim3 t256(256);

    // ---- CSR build + weight splits (small, one pass) ----
    csr_build<<<BB, t256>>>(ei);
    split_kernel<<<(FIN * CC / 4) / 256, t256>>>(W1, w1h, w1l, FIN * CC / 4);
    split_kernel<<<(CC * CC / 4) / 256, t256>>>(W2, w2h, w2l, CC * CC / 4);
    split_kernel<<<(CC * CC / 4) / 256, t256>>>(p1_tw, p1h, p1l, CC * CC / 4);
    split_kernel<<<(CC * CC / 4) / 256, t256>>>(p2_tw, p2h, p2l, CC * CC / 4);

    // ---- GAT layer 1 (GEMM emits es/ed in epilogue) ----
    tf32_gemm<<<dim3(CC / 128, NN / 128), t256>>>(x, w1h, w1l, nullptr, hlin,
                                                  NN, CC, FIN, asrc1, adst1, es, ed);
    gat_fused<<<(NN * 32) / 256, t256>>>(off, csrc, es, ed, hlin, b1, hout);

    // ---- GAT layer 2 ----
    tf32_gemm<<<dim3(CC / 128, NN / 128), t256>>>(hout, w2h, w2l, nullptr, hlin,
                                                  NN, CC, CC, asrc2, adst2, es, ed);
    gat_fused<<<(NN * 32) / 256, t256>>>(off, csrc, es, ed, hlin, b2, hout);

    // ---- Pool 1 (top-256 of 512 per graph) ----
    pool_fused<NPG, K1><<<BB, NPG>>>(hout, p1_sw, selb);
    tf32_gemm<<<dim3(CC / 128, (BB * K1) / 128), t256>>>(selb, p1h, p1l, p1_tb, pool1,
                                                         BB * K1, CC, CC,
                                                         nullptr, nullptr, nullptr, nullptr);

    // ---- Pool 2 (top-128 of 256 per graph) ----
    pool_fused<K1, K2><<<BB, K1>>>(pool1, p2_sw, selb);
    tf32_gemm<<<dim3(CC / 128, (BB * K2) / 128), t256>>>(selb, p2h, p2l, p2_tb, pool2,
                                                         BB * K2, CC, CC,
                                                         nullptr, nullptr, nullptr, nullptr);

    // ---- readout ----
    readout_fused<<<BB, t256>>>(pool2, c1w, c1b, c2w, c2b, out);
}

// round 16
// speedup vs baseline: 1.1580x; 1.0155x over previous
#include <cuda_runtime.h>
#include <cuda_bf16.h>
#include <cstdint>

// Problem constants
#define NN   32768
#define FIN  128
#define CC   256
#define HH   4
#define FH   64
#define EE   524288
#define BB   64
#define NPG  512
#define EPG  (EE / BB)
#define K1   256
#define K2   128

// ---------------- scratch (device globals; no allocation allowed) ----------
__device__ float    g_hlin[NN * CC];
__device__ float    g_hout[NN * CC];
__device__ float    g_es[NN * HH];
__device__ float    g_ed[NN * HH];
__device__ int      g_off[NN + 1];
__device__ int      g_csrc[EE];
__device__ float    g_sel[(BB * K1) * CC];
__device__ float    g_pool1[(BB * K1) * CC];
__device__ float    g_pool2[(BB * K2) * CC];
// pre-split tf32 weight buffers (hi/lo)
__device__ float    g_w1h[FIN * CC];
__device__ float    g_w1l[FIN * CC];
__device__ float    g_w2h[CC * CC];
__device__ float    g_w2l[CC * CC];
__device__ float    g_p1h[CC * CC];
__device__ float    g_p1l[CC * CC];
__device__ float    g_p2h[CC * CC];
__device__ float    g_p2l[CC * CC];

__device__ __forceinline__ float leaky(float x) { return x > 0.f ? x : 0.2f * x; }

// ---------------- tf32 helpers ----------------------------------------------
__device__ __forceinline__ float tf32r(float x) {
    uint32_t u;
    asm("cvt.rna.tf32.f32 %0, %1;" : "=r"(u) : "f"(x));
    return __uint_as_float(u);
}
__device__ __forceinline__ void split4(const float4 v, float4& h, float4& l) {
    h.x = tf32r(v.x); l.x = v.x - h.x;
    h.y = tf32r(v.y); l.y = v.y - h.y;
    h.z = tf32r(v.z); l.z = v.z - h.z;
    h.w = tf32r(v.w); l.w = v.w - h.w;
}
__device__ __forceinline__ void mma8(float4& d, const uint32_t* a, const uint32_t* b) {
    asm volatile("mma.sync.aligned.m16n8k8.row.col.f32.tf32.tf32.f32 "
        "{%0,%1,%2,%3}, {%4,%5,%6,%7}, {%8,%9}, {%0,%1,%2,%3};"
        : "+f"(d.x), "+f"(d.y), "+f"(d.z), "+f"(d.w)
        : "r"(a[0]), "r"(a[1]), "r"(a[2]), "r"(a[3]), "r"(b[0]), "r"(b[1]));
}

// ---------------- single-launch weight split kernel --------------------------
// W1: 8192 f4; W2/p1_tw/p2_tw: 16384 f4 each. Total 57344 f4 -> 224 CTAs.
__global__ void split_all(const float* __restrict__ W1, const float* __restrict__ W2,
                          const float* __restrict__ P1, const float* __restrict__ P2,
                          float* __restrict__ w1h, float* __restrict__ w1l,
                          float* __restrict__ w2h, float* __restrict__ w2l,
                          float* __restrict__ p1h, float* __restrict__ p1l,
                          float* __restrict__ p2h, float* __restrict__ p2l) {
    const int i = blockIdx.x * blockDim.x + threadIdx.x;
    const float* src; float* hi; float* lo; int off;
    if (i < 8192)       { src = W1; hi = w1h; lo = w1l; off = i; }
    else if (i < 24576) { src = W2; hi = w2h; lo = w2l; off = i - 8192; }
    else if (i < 40960) { src = P1; hi = p1h; lo = p1l; off = i - 24576; }
    else                { src = P2; hi = p2h; lo = p2l; off = i - 40960; }
    float4 h, l;
    split4(((const float4*)src)[off], h, l);
    ((float4*)hi)[off] = h;
    ((float4*)lo)[off] = l;
}

// ---------------- 3xTF32 GEMM, double-buffered smem --------------------------
// C[M,N]=A@B (+bias). A split in-kernel; B (weights) pre-split. 128x128 CTA
// tile, 256 threads (2x4 warps of 64x32), BK=16, 1 sync per k-tile.
// Optional fused es/ed epilogue (GAT GEMMs, N==256, bias null).
#define ASTR 20
#define BSTR 136
#define A_ELEMS (128 * ASTR)     // 2560 floats per buffer
#define B_ELEMS (16 * BSTR)      // 2176 floats per buffer
#define GEMM_SMEM ((2 * A_ELEMS * 2 + 2 * B_ELEMS * 2) * 4)   // 75776 bytes
__global__ void __launch_bounds__(256)
tf32_gemm(const float* __restrict__ A,
          const float* __restrict__ Bh, const float* __restrict__ Bl,
          const float* __restrict__ bias, float* __restrict__ Cm,
          int M, int N, int K,
          const float* __restrict__ a_src, const float* __restrict__ a_dst,
          float* __restrict__ es, float* __restrict__ ed) {
    extern __shared__ float smem[];
    float* As_hi = smem;                       // [2][A_ELEMS]
    float* As_lo = smem + 2 * A_ELEMS;         // [2][A_ELEMS]
    float* Bs_hi = smem + 4 * A_ELEMS;         // [2][B_ELEMS]
    float* Bs_lo = smem + 4 * A_ELEMS + 2 * B_ELEMS;

    const int tid = threadIdx.x;
    const int lane = tid & 31, wid = tid >> 5;
    const int warp_m = wid & 1, warp_n = wid >> 1;
    const int g = lane >> 2, t = lane & 3;
    const int wm0 = warp_m * 64, wn0 = warp_n * 32;
    const int row0 = blockIdx.y * 128;
    const int col0 = blockIdx.x * 128;

    const int arow0 = tid >> 2, ac0 = (tid & 3) << 2;
    const int arow1 = arow0 + 64;
    const int brow0 = tid >> 5, bc0 = (tid & 31) << 2;
    const int brow1 = brow0 + 8;

    float4 acc[4][4];
#pragma unroll
    for (int i = 0; i < 4; i++)
#pragma unroll
        for (int j = 0; j < 4; j++) acc[i][j] = make_float4(0.f, 0.f, 0.f, 0.f);

    const int ntiles = K >> 4;
    float4 pa0, pa1, pbh0, pbh1, pbl0, pbl1;
    pa0 = *(const float4*)&A[(size_t)(row0 + arow0) * K + ac0];
    pa1 = *(const float4*)&A[(size_t)(row0 + arow1) * K + ac0];
    pbh0 = *(const float4*)&Bh[(size_t)brow0 * N + col0 + bc0];
    pbh1 = *(const float4*)&Bh[(size_t)brow1 * N + col0 + bc0];
    pbl0 = *(const float4*)&Bl[(size_t)brow0 * N + col0 + bc0];
    pbl1 = *(const float4*)&Bl[(size_t)brow1 * N + col0 + bc0];

    // stage tile 0 into buffer 0
    {
        float4 h, l;
        split4(pa0, h, l);
        *(float4*)&As_hi[arow0 * ASTR + ac0] = h;
        *(float4*)&As_lo[arow0 * ASTR + ac0] = l;
        split4(pa1, h, l);
        *(float4*)&As_hi[arow1 * ASTR + ac0] = h;
        *(float4*)&As_lo[arow1 * ASTR + ac0] = l;
        *(float4*)&Bs_hi[brow0 * BSTR + bc0] = pbh0;
        *(float4*)&Bs_hi[brow1 * BSTR + bc0] = pbh1;
        *(float4*)&Bs_lo[brow0 * BSTR + bc0] = pbl0;
        *(float4*)&Bs_lo[brow1 * BSTR + bc0] = pbl1;
    }
    __syncthreads();

    int buf = 0;
    for (int kt = 0; kt < ntiles; kt++) {
        if (kt + 1 < ntiles) {
            const int k0 = (kt + 1) << 4;
            pa0 = *(const float4*)&A[(size_t)(row0 + arow0) * K + k0 + ac0];
            pa1 = *(const float4*)&A[(size_t)(row0 + arow1) * K + k0 + ac0];
            pbh0 = *(const float4*)&Bh[(size_t)(k0 + brow0) * N + col0 + bc0];
            pbh1 = *(const float4*)&Bh[(size_t)(k0 + brow1) * N + col0 + bc0];
            pbl0 = *(const float4*)&Bl[(size_t)(k0 + brow0) * N + col0 + bc0];
            pbl1 = *(const float4*)&Bl[(size_t)(k0 + brow1) * N + col0 + bc0];
        }
        const uint32_t* AhS = (const uint32_t*)(As_hi + buf * A_ELEMS);
        const uint32_t* AlS = (const uint32_t*)(As_lo + buf * A_ELEMS);
        const uint32_t* BhS = (const uint32_t*)(Bs_hi + buf * B_ELEMS);
        const uint32_t* BlS = (const uint32_t*)(Bs_lo + buf * B_ELEMS);
#pragma unroll
        for (int k8 = 0; k8 < 16; k8 += 8) {
            uint32_t af[4][4], bh[4][2], bl[4][2];
#pragma unroll
            for (int nt = 0; nt < 4; nt++) {
                const int c = wn0 + nt * 8 + g;
                bh[nt][0] = BhS[(k8 + t) * BSTR + c];
                bh[nt][1] = BhS[(k8 + t + 4) * BSTR + c];
                bl[nt][0] = BlS[(k8 + t) * BSTR + c];
                bl[nt][1] = BlS[(k8 + t + 4) * BSTR + c];
            }
#pragma unroll
            for (int mt = 0; mt < 4; mt++) {
                const int r = wm0 + mt * 16 + g;
                af[mt][0] = AhS[r * ASTR + k8 + t];
                af[mt][1] = AhS[(r + 8) * ASTR + k8 + t];
                af[mt][2] = AhS[r * ASTR + k8 + t + 4];
                af[mt][3] = AhS[(r + 8) * ASTR + k8 + t + 4];
            }
#pragma unroll
            for (int mt = 0; mt < 4; mt++)
#pragma unroll
                for (int nt = 0; nt < 4; nt++) {
                    mma8(acc[mt][nt], af[mt], bh[nt]);
                    mma8(acc[mt][nt], af[mt], bl[nt]);
                }
#pragma unroll
            for (int mt = 0; mt < 4; mt++) {
                const int r = wm0 + mt * 16 + g;
                af[mt][0] = AlS[r * ASTR + k8 + t];
                af[mt][1] = AlS[(r + 8) * ASTR + k8 + t];
                af[mt][2] = AlS[r * ASTR + k8 + t + 4];
                af[mt][3] = AlS[(r + 8) * ASTR + k8 + t + 4];
            }
#pragma unroll
            for (int mt = 0; mt < 4; mt++)
#pragma unroll
                for (int nt = 0; nt < 4; nt++)
                    mma8(acc[mt][nt], af[mt], bh[nt]);
        }
        if (kt + 1 < ntiles) {
            const int nb = buf ^ 1;
            float* Ah2 = As_hi + nb * A_ELEMS;
            float* Al2 = As_lo + nb * A_ELEMS;
            float* Bh2 = Bs_hi + nb * B_ELEMS;
            float* Bl2 = Bs_lo + nb * B_ELEMS;
            float4 h, l;
            split4(pa0, h, l);
            *(float4*)&Ah2[arow0 * ASTR + ac0] = h;
            *(float4*)&Al2[arow0 * ASTR + ac0] = l;
            split4(pa1, h, l);
            *(float4*)&Ah2[arow1 * ASTR + ac0] = h;
            *(float4*)&Al2[arow1 * ASTR + ac0] = l;
            *(float4*)&Bh2[brow0 * BSTR + bc0] = pbh0;
            *(float4*)&Bh2[brow1 * BSTR + bc0] = pbh1;
            *(float4*)&Bl2[brow0 * BSTR + bc0] = pbl0;
            *(float4*)&Bl2[brow1 * BSTR + bc0] = pbl1;
            __syncthreads();
            buf = nb;
        }
    }

    // store C (+bias)
#pragma unroll
    for (int nt = 0; nt < 4; nt++) {
        const int c = col0 + wn0 + nt * 8 + 2 * t;
        float2 bv = make_float2(0.f, 0.f);
        if (bias) bv = *(const float2*)&bias[c];
#pragma unroll
        for (int mt = 0; mt < 4; mt++) {
            const int r = row0 + wm0 + mt * 16 + g;
            float2 lo2 = make_float2(acc[mt][nt].x + bv.x, acc[mt][nt].y + bv.y);
            float2 hi2 = make_float2(acc[mt][nt].z + bv.x, acc[mt][nt].w + bv.y);
            *(float2*)&Cm[(size_t)r * N + c] = lo2;
            *(float2*)&Cm[(size_t)(r + 8) * N + c] = hi2;
        }
    }

    // ---- fused es/ed epilogue (GAT layer GEMMs only) ----
    if (a_src) {
        __syncthreads();
        float* es_s = As_hi;          // [128][2]
        float* ed_s = As_hi + 256;
        for (int i = tid; i < 512; i += 256) As_hi[i] = 0.f;
        __syncthreads();
        const int lh = wn0 >> 6;
        float asv[4][2], adv[4][2];
#pragma unroll
        for (int nt = 0; nt < 4; nt++) {
            const int gc = col0 + wn0 + nt * 8 + 2 * t;
            asv[nt][0] = a_src[gc];     asv[nt][1] = a_src[gc + 1];
            adv[nt][0] = a_dst[gc];     adv[nt][1] = a_dst[gc + 1];
        }
#pragma unroll
        for (int mt = 0; mt < 4; mt++) {
            float se1 = 0.f, de1 = 0.f, se2 = 0.f, de2 = 0.f;
#pragma unroll
            for (int nt = 0; nt < 4; nt++) {
                se1 += acc[mt][nt].x * asv[nt][0] + acc[mt][nt].y * asv[nt][1];
                de1 += acc[mt][nt].x * adv[nt][0] + acc[mt][nt].y * adv[nt][1];
                se2 += acc[mt][nt].z * asv[nt][0] + acc[mt][nt].w * asv[nt][1];
                de2 += acc[mt][nt].z * adv[nt][0] + acc[mt][nt].w * adv[nt][1];
            }
#pragma unroll
            for (int m = 1; m < 4; m <<= 1) {
                se1 += __shfl_xor_sync(0xffffffffu, se1, m);
                de1 += __shfl_xor_sync(0xffffffffu, de1, m);
                se2 += __shfl_xor_sync(0xffffffffu, se2, m);
                de2 += __shfl_xor_sync(0xffffffffu, de2, m);
            }
            if (t == 0) {
                const int r1 = wm0 + mt * 16 + g;
                atomicAdd(&es_s[r1 * 2 + lh], se1);
                atomicAdd(&ed_s[r1 * 2 + lh], de1);
                atomicAdd(&es_s[(r1 + 8) * 2 + lh], se2);
                atomicAdd(&ed_s[(r1 + 8) * 2 + lh], de2);
            }
        }
        __syncthreads();
        const int r = tid >> 1, l = tid & 1;
        const int h0 = col0 >> 6;
        es[(size_t)(row0 + r) * HH + h0 + l] = es_s[r * 2 + l];
        ed[(size_t)(row0 + r) * HH + h0 + l] = ed_s[r * 2 + l];
    }
}

// ---------------- single-kernel CSR build (1 CTA per graph) -----------------
__global__ void __launch_bounds__(256)
csr_build(const int* __restrict__ ei) {
    __shared__ int cnt[NPG];
    __shared__ int sh[256];
    const int g = blockIdx.x, tid = threadIdx.x;
    const int ebase = g * EPG, nbase = g * NPG;
    cnt[tid] = 0; cnt[tid + 256] = 0;
    __syncthreads();
#pragma unroll
    for (int i = tid; i < EPG; i += 256)
        atomicAdd(&cnt[ei[EE + ebase + i] - nbase], 1);
    __syncthreads();
    const int c0 = cnt[2 * tid], c1 = cnt[2 * tid + 1];
    const int tot = c0 + c1;
    sh[tid] = tot;
    __syncthreads();
    for (int s = 1; s < 256; s <<= 1) {
        const int v = (tid >= s) ? sh[tid - s] : 0;
        __syncthreads();
        sh[tid] += v;
        __syncthreads();
    }
    const int base = sh[tid] - tot;
    g_off[nbase + 2 * tid]     = ebase + base;
    g_off[nbase + 2 * tid + 1] = ebase + base + c0;
    cnt[2 * tid] = base;
    cnt[2 * tid + 1] = base + c0;
    if (g == BB - 1 && tid == 0) g_off[NN] = EE;
    __syncthreads();
#pragma unroll
    for (int i = tid; i < EPG; i += 256) {
        const int d = ei[EE + ebase + i] - nbase;
        const int p = atomicAdd(&cnt[d], 1);
        g_csrc[ebase + p] = ei[ebase + i];
    }
}

// ---------------- fused softmax + aggregate + bias + ELU (R10-proven) -------
__global__ void __launch_bounds__(256)
gat_fused(const int* __restrict__ off, const int* __restrict__ csrc,
          const float* __restrict__ es, const float* __restrict__ ed,
          const float* __restrict__ hlin, const float* __restrict__ bias,
          float* __restrict__ out) {
    const int n = (blockIdx.x * blockDim.x + threadIdx.x) >> 5;
    const int lane = threadIdx.x & 31;
    if (n >= NN) return;

    const float4 edv = ((const float4*)ed)[n];
    const float4 esv = ((const float4*)es)[n];
    const float xs0 = __expf(leaky(esv.x + edv.x));
    const float xs1 = __expf(leaky(esv.y + edv.y));
    const float xs2 = __expf(leaky(esv.z + edv.z));
    const float xs3 = __expf(leaky(esv.w + edv.w));

    const int hi = lane >> 4;
    const float4* hn = (const float4*)(hlin + (size_t)n * CC);
    float4 acc0 = hn[lane];
    float4 acc1 = hn[32 + lane];
    const float sa0 = hi ? xs1 : xs0;
    const float sa1 = hi ? xs3 : xs2;
    acc0.x *= sa0; acc0.y *= sa0; acc0.z *= sa0; acc0.w *= sa0;
    acc1.x *= sa1; acc1.y *= sa1; acc1.z *= sa1; acc1.w *= sa1;

    float ts0 = 0.f, ts1 = 0.f, ts2 = 0.f, ts3 = 0.f;
    const int o0 = off[n], o1 = off[n + 1];
    for (int base = o0; base < o1; base += 32) {
        const int cnt = min(32, o1 - base);
        int s = 0;
        float t0 = 0.f, t1 = 0.f, t2 = 0.f, t3 = 0.f;
        if (lane < cnt) {
            s = csrc[base + lane];
            const float4 ess = ((const float4*)es)[s];
            t0 = __expf(leaky(ess.x + edv.x));
            t1 = __expf(leaky(ess.y + edv.y));
            t2 = __expf(leaky(ess.z + edv.z));
            t3 = __expf(leaky(ess.w + edv.w));
        }
        ts0 += t0; ts1 += t1; ts2 += t2; ts3 += t3;

        int se = __shfl_sync(0xffffffffu, s, 0);
        const float4* hs = (const float4*)(hlin + (size_t)se * CC);
        float4 v0n = hs[lane], v1n = hs[32 + lane];
        for (int e = 0; e < cnt; e++) {
            const float4 v0 = v0n, v1 = v1n;
            const float w0 = __shfl_sync(0xffffffffu, t0, e);
            const float w1 = __shfl_sync(0xffffffffu, t1, e);
            const float w2 = __shfl_sync(0xffffffffu, t2, e);
            const float w3 = __shfl_sync(0xffffffffu, t3, e);
            if (e + 1 < cnt) {
                se = __shfl_sync(0xffffffffu, s, e + 1);
                const float4* hsn = (const float4*)(hlin + (size_t)se * CC);
                v0n = hsn[lane]; v1n = hsn[32 + lane];
            }
            const float aw0 = hi ? w1 : w0;
            const float aw1 = hi ? w3 : w2;
            acc0.x += aw0 * v0.x; acc0.y += aw0 * v0.y;
            acc0.z += aw0 * v0.z; acc0.w += aw0 * v0.w;
            acc1.x += aw1 * v1.x; acc1.y += aw1 * v1.y;
            acc1.z += aw1 * v1.z; acc1.w += aw1 * v1.w;
        }
    }
#pragma unroll
    for (int o = 16; o; o >>= 1) {
        ts0 += __shfl_xor_sync(0xffffffffu, ts0, o);
        ts1 += __shfl_xor_sync(0xffffffffu, ts1, o);
        ts2 += __shfl_xor_sync(0xffffffffu, ts2, o);
        ts3 += __shfl_xor_sync(0xffffffffu, ts3, o);
    }
    const float di0 = 1.f / (xs0 + ts0 + 1e-16f);
    const float di1 = 1.f / (xs1 + ts1 + 1e-16f);
    const float di2 = 1.f / (xs2 + ts2 + 1e-16f);
    const float di3 = 1.f / (xs3 + ts3 + 1e-16f);
    const float d0 = hi ? di1 : di0;
    const float d1 = hi ? di3 : di2;

    const float4 bv0 = ((const float4*)bias)[lane];
    const float4 bv1 = ((const float4*)bias)[32 + lane];
    float4 o0v, o1v;
    o0v.x = acc0.x * d0 + bv0.x; o0v.y = acc0.y * d0 + bv0.y;
    o0v.z = acc0.z * d0 + bv0.z; o0v.w = acc0.w * d0 + bv0.w;
    o1v.x = acc1.x * d1 + bv1.x; o1v.y = acc1.y * d1 + bv1.y;
    o1v.z = acc1.z * d1 + bv1.z; o1v.w = acc1.w * d1 + bv1.w;
    o0v.x = o0v.x > 0.f ? o0v.x : (__expf(o0v.x) - 1.f);
    o0v.y = o0v.y > 0.f ? o0v.y : (__expf(o0v.y) - 1.f);
    o0v.z = o0v.z > 0.f ? o0v.z : (__expf(o0v.z) - 1.f);
    o0v.w = o0v.w > 0.f ? o0v.w : (__expf(o0v.w) - 1.f);
    o1v.x = o1v.x > 0.f ? o1v.x : (__expf(o1v.x) - 1.f);
    o1v.y = o1v.y > 0.f ? o1v.y : (__expf(o1v.y) - 1.f);
    o1v.z = o1v.z > 0.f ? o1v.z : (__expf(o1v.z) - 1.f);
    o1v.w = o1v.w > 0.f ? o1v.w : (__expf(o1v.w) - 1.f);
    ((float4*)out)[(size_t)n * 64 + lane]      = o0v;
    ((float4*)out)[(size_t)n * 64 + 32 + lane] = o1v;
}

// ---------------- fused pooling: score + top-k + gather ---------------------
template <int NPB, int KSEL>
__global__ void pool_fused(const float* __restrict__ X, const float* __restrict__ sw,
                           float* __restrict__ selb) {
    __shared__ float sv[NPB];
    __shared__ int si[NPB];
    const int b = blockIdx.x, t = threadIdx.x;
    const int wid = t >> 5, lane = t & 31;

#pragma unroll
    for (int rr = 0; rr < 32; rr++) {
        const int local = wid * 32 + rr;
        const float* xp = X + (size_t)(b * NPB + local) * CC;
        float s = 0.f;
#pragma unroll
        for (int c = 0; c < CC / 32; c++) s += xp[lane + c * 32] * sw[lane + c * 32];
#pragma unroll
        for (int o = 16; o; o >>= 1) s += __shfl_xor_sync(0xffffffffu, s, o);
        if (lane == 0) { sv[local] = s; si[local] = local; }
    }
    __syncthreads();

    for (int k = 2; k <= NPB; k <<= 1) {
        for (int j = k >> 1; j > 0; j >>= 1) {
            const int ixj = t ^ j;
            if (ixj > t) {
                const bool desc = ((t & k) == 0);
                const float a = sv[t], c = sv[ixj];
                if ((a < c) == desc) {
                    sv[t] = c; sv[ixj] = a;
                    const int tmp = si[t]; si[t] = si[ixj]; si[ixj] = tmp;
                }
            }
            __syncthreads();
        }
    }

    for (int idx = t; idx < KSEL * 64; idx += NPB) {
        const int r = idx >> 6, q = idx & 63;
        const int src = b * NPB + si[r];
        ((float4*)selb)[(size_t)(b * KSEL + r) * 64 + q] =
            ((const float4*)X)[(size_t)src * 64 + q];
    }
}

// ---------------- fused readout: mean + fc1(relu) + fc2 + log_softmax -------
__global__ void __launch_bounds__(256)
readout_fused(const float* __restrict__ X, const float* __restrict__ c1w,
              const float* __restrict__ c1b, const float* __restrict__ c2w,
              const float* __restrict__ c2b, float* __restrict__ out) {
    __shared__ float gm[CC];
    __shared__ float f1[64];
    const int b = blockIdx.x, t = threadIdx.x;
    const int wid = t >> 5, lane = t & 31;

    float s = 0.f;
    const float* xp = X + (size_t)b * K2 * CC + t;
#pragma unroll 4
    for (int r = 0; r < K2; r++) s += xp[r * CC];
    gm[t] = s * (1.f / K2);
    __syncthreads();

#pragma unroll
    for (int oo = 0; oo < 8; oo++) {
        const int o = wid * 8 + oo;
        float acc = 0.f;
#pragma unroll
        for (int c = 0; c < CC / 32; c++)
            acc += gm[lane + c * 32] * c1w[(lane + c * 32) * 64 + o];
#pragma unroll
        for (int off = 16; off; off >>= 1) acc += __shfl_xor_sync(0xffffffffu, acc, off);
        if (lane == 0) {
            const float v = acc + c1b[o];
            f1[o] = v > 0.f ? v : 0.f;
        }
    }
    __syncthreads();

    if (wid == 0) {
        float l0 = 0.f, l1 = 0.f;
#pragma unroll
        for (int k = lane; k < 64; k += 32) {
            const float v = f1[k];
            l0 += v * c2w[k * 2 + 0];
            l1 += v * c2w[k * 2 + 1];
        }
#pragma unroll
        for (int off = 16; off; off >>= 1) {
            l0 += __shfl_xor_sync(0xffffffffu, l0, off);
            l1 += __shfl_xor_sync(0xffffffffu, l1, off);
        }
        if (lane == 0) {
            l0 += c2b[0]; l1 += c2b[1];
            const float mm = fmaxf(l0, l1);
            const float lse = mm + logf(__expf(l0 - mm) + __expf(l1 - mm));
            out[b * 2 + 0] = l0 - lse;
            out[b * 2 + 1] = l1 - lse;
        }
    }
}

// ---------------- host orchestration ----------------------------------------
static float* sym(const void* s) {
    void* p = nullptr;
    cudaGetSymbolAddress(&p, (const void*)s);
    return (float*)p;
}

extern "C" void kernel_launch(void* const* d_in, const int* in_sizes, int n_in,
                              void* d_out, int out_size) {
    const float* x      = (const float*)d_in[0];
    const int*   ei     = (const int*)  d_in[1];
    const float* W1     = (const float*)d_in[3];
    const float* asrc1  = (const float*)d_in[4];
    const float* adst1  = (const float*)d_in[5];
    const float* b1     = (const float*)d_in[6];
    const float* W2     = (const float*)d_in[7];
    const float* asrc2  = (const float*)d_in[8];
    const float* adst2  = (const float*)d_in[9];
    const float* b2     = (const float*)d_in[10];
    const float* p1_sw  = (const float*)d_in[11];
    const float* p1_tw  = (const float*)d_in[13];
    const float* p1_tb  = (const float*)d_in[14];
    const float* p2_sw  = (const float*)d_in[15];
    const float* p2_tw  = (const float*)d_in[17];
    const float* p2_tb  = (const float*)d_in[18];
    const float* c1w    = (const float*)d_in[19];
    const float* c1b    = (const float*)d_in[20];
    const float* c2w    = (const float*)d_in[21];
    const float* c2b    = (const float*)d_in[22];
    float* out = (float*)d_out;

    float* hlin  = sym(g_hlin);
    float* hout  = sym(g_hout);
    float* es    = sym(g_es);
    float* ed    = sym(g_ed);
    int*   off   = (int*)sym(g_off);
    int*   csrc  = (int*)sym(g_csrc);
    float* selb  = sym(g_sel);
    float* pool1 = sym(g_pool1);
    float* pool2 = sym(g_pool2);
    float* w1h = sym(g_w1h), *w1l = sym(g_w1l);
    float* w2h = sym(g_w2h), *w2l = sym(g_w2l);
    float* p1h = sym(g_p1h), *p1l = sym(g_p1l);
    float* p2h = sym(g_p2h), *p2l = sym(g_p2l);

    cudaFuncSetAttribute(tf32_gemm, cudaFuncAttributeMaxDynamicSharedMemorySize,
                         GEMM_SMEM);

    dim3 t256(256);

    // ---- CSR build + single-launch weight split ----
    csr_build<<<BB, t256>>>(ei);
    split_all<<<224, t256>>>(W1, W2, p1_tw, p2_tw, w1h, w1l, w2h, w2l,
                             p1h, p1l, p2h, p2l);

    // ---- GAT layer 1 (GEMM emits es/ed in epilogue) ----
    tf32_gemm<<<dim3(CC / 128, NN / 128), t256, GEMM_SMEM>>>(
        x, w1h, w1l, nullptr, hlin, NN, CC, FIN, asrc1, adst1, es, ed);
    gat_fused<<<(NN * 32) / 256, t256>>>(off, csrc, es, ed, hlin, b1, hout);

    // ---- GAT layer 2 ----
    tf32_gemm<<<dim3(CC / 128, NN / 128), t256, GEMM_SMEM>>>(
        hout, w2h, w2l, nullptr, hlin, NN, CC, CC, asrc2, adst2, es, ed);
    gat_fused<<<(NN * 32) / 256, t256>>>(off, csrc, es, ed, hlin, b2, hout);

    // ---- Pool 1 (top-256 of 512 per graph) ----
    pool_fused<NPG, K1><<<BB, NPG>>>(hout, p1_sw, selb);
    tf32_gemm<<<dim3(CC / 128, (BB * K1) / 128), t256, GEMM_SMEM>>>(
        selb, p1h, p1l, p1_tb, pool1, BB * K1, CC, CC,
        nullptr, nullptr, nullptr, nullptr);

    // ---- Pool 2 (top-128 of 256 per graph) ----
    pool_fused<K1, K2><<<BB, K1>>>(pool1, p2_sw, selb);
    tf32_gemm<<<dim3(CC / 128, (BB * K2) / 128), t256, GEMM_SMEM>>>(
        selb, p2h, p2l, p2_tb, pool2, BB * K2, CC, CC,
        nullptr, nullptr, nullptr, nullptr);

    // ---- readout ----
    readout_fused<<<BB, t256>>>(pool2, c1w, c1b, c2w, c2b, out);
}

// round 17
// speedup vs baseline: 1.2121x; 1.0467x over previous
#include <cuda_runtime.h>
#include <cuda_bf16.h>
#include <cstdint>

// Problem constants
#define NN   32768
#define FIN  128
#define CC   256
#define HH   4
#define FH   64
#define EE   524288
#define BB   64
#define NPG  512
#define EPG  (EE / BB)
#define K1   256
#define K2   128

// ---------------- scratch (device globals; no allocation allowed) ----------
__device__ float    g_hlin[NN * CC];
__device__ float    g_hout[NN * CC];
__device__ float    g_es[NN * HH];
__device__ float    g_ed[NN * HH];
__device__ int      g_off[NN + 1];
__device__ int      g_csrc[EE];
__device__ float    g_sel[(BB * K1) * CC];
__device__ float    g_pool1[(BB * K1) * CC];
__device__ float    g_pool2[(BB * K2) * CC];
// pre-split tf32 weight buffers (hi/lo)
__device__ float    g_w1h[FIN * CC];
__device__ float    g_w1l[FIN * CC];
__device__ float    g_w2h[CC * CC];
__device__ float    g_w2l[CC * CC];
__device__ float    g_p1h[CC * CC];
__device__ float    g_p1l[CC * CC];
__device__ float    g_p2h[CC * CC];
__device__ float    g_p2l[CC * CC];

__device__ __forceinline__ float leaky(float x) { return x > 0.f ? x : 0.2f * x; }

// ---------------- tf32 / async helpers ---------------------------------------
__device__ __forceinline__ float tf32r(float x) {
    uint32_t u;
    asm("cvt.rna.tf32.f32 %0, %1;" : "=r"(u) : "f"(x));
    return __uint_as_float(u);
}
__device__ __forceinline__ void split4(const float4 v, float4& h, float4& l) {
    h.x = tf32r(v.x); l.x = v.x - h.x;
    h.y = tf32r(v.y); l.y = v.y - h.y;
    h.z = tf32r(v.z); l.z = v.z - h.z;
    h.w = tf32r(v.w); l.w = v.w - h.w;
}
__device__ __forceinline__ void mma8(float4& d, const uint32_t* a, const uint32_t* b) {
    asm volatile("mma.sync.aligned.m16n8k8.row.col.f32.tf32.tf32.f32 "
        "{%0,%1,%2,%3}, {%4,%5,%6,%7}, {%8,%9}, {%0,%1,%2,%3};"
        : "+f"(d.x), "+f"(d.y), "+f"(d.z), "+f"(d.w)
        : "r"(a[0]), "r"(a[1]), "r"(a[2]), "r"(a[3]), "r"(b[0]), "r"(b[1]));
}
__device__ __forceinline__ uint32_t smem_u32(const void* p) {
    uint32_t a;
    asm("{ .reg .u64 t; cvta.to.shared.u64 t, %1; cvt.u32.u64 %0, t; }" : "=r"(a) : "l"(p));
    return a;
}
__device__ __forceinline__ void cpasync16(uint32_t s, const void* g) {
    asm volatile("cp.async.ca.shared.global [%0], [%1], 16;" :: "r"(s), "l"(g));
}
#define CP_COMMIT() asm volatile("cp.async.commit_group;" ::: "memory")
#define CP_WAIT0()  asm volatile("cp.async.wait_group 0;" ::: "memory")

// ---------------- merged prep: CSR build (blocks 0-63) + weight split --------
__global__ void __launch_bounds__(256)
prep_kernel(const int* __restrict__ ei,
            const float* __restrict__ W1, const float* __restrict__ W2,
            const float* __restrict__ P1, const float* __restrict__ P2,
            float* __restrict__ w1h, float* __restrict__ w1l,
            float* __restrict__ w2h, float* __restrict__ w2l,
            float* __restrict__ p1h, float* __restrict__ p1l,
            float* __restrict__ p2h, float* __restrict__ p2l) {
    const int tid = threadIdx.x;
    if (blockIdx.x >= BB) {
        // weight split: blocks 64..287 cover 57344 float4s
        const int i = (blockIdx.x - BB) * 256 + tid;
        const float* src; float* hi; float* lo; int off;
        if (i < 8192)       { src = W1; hi = w1h; lo = w1l; off = i; }
        else if (i < 24576) { src = W2; hi = w2h; lo = w2l; off = i - 8192; }
        else if (i < 40960) { src = P1; hi = p1h; lo = p1l; off = i - 24576; }
        else                { src = P2; hi = p2h; lo = p2l; off = i - 40960; }
        float4 h, l;
        split4(((const float4*)src)[off], h, l);
        ((float4*)hi)[off] = h;
        ((float4*)lo)[off] = l;
        return;
    }
    __shared__ int cnt[NPG];
    __shared__ int sh[256];
    const int g = blockIdx.x;
    const int ebase = g * EPG, nbase = g * NPG;
    cnt[tid] = 0; cnt[tid + 256] = 0;
    __syncthreads();
#pragma unroll
    for (int i = tid; i < EPG; i += 256)
        atomicAdd(&cnt[ei[EE + ebase + i] - nbase], 1);
    __syncthreads();
    const int c0 = cnt[2 * tid], c1 = cnt[2 * tid + 1];
    const int tot = c0 + c1;
    sh[tid] = tot;
    __syncthreads();
    for (int s = 1; s < 256; s <<= 1) {
        const int v = (tid >= s) ? sh[tid - s] : 0;
        __syncthreads();
        sh[tid] += v;
        __syncthreads();
    }
    const int base = sh[tid] - tot;
    g_off[nbase + 2 * tid]     = ebase + base;
    g_off[nbase + 2 * tid + 1] = ebase + base + c0;
    cnt[2 * tid] = base;
    cnt[2 * tid + 1] = base + c0;
    if (g == BB - 1 && tid == 0) g_off[NN] = EE;
    __syncthreads();
#pragma unroll
    for (int i = tid; i < EPG; i += 256) {
        const int d = ei[EE + ebase + i] - nbase;
        const int p = atomicAdd(&cnt[d], 1);
        g_csrc[ebase + p] = ei[ebase + i];
    }
}

// ---------------- 3xTF32 GEMM, double-buffered, cp.async B staging -----------
#define ASTR 20
#define BSTR 136
#define A_ELEMS (128 * ASTR)
#define B_ELEMS (16 * BSTR)
#define GEMM_SMEM ((2 * A_ELEMS * 2 + 2 * B_ELEMS * 2) * 4)   // 75776 bytes
__global__ void __launch_bounds__(256)
tf32_gemm(const float* __restrict__ A,
          const float* __restrict__ Bh, const float* __restrict__ Bl,
          const float* __restrict__ bias, float* __restrict__ Cm,
          int M, int N, int K,
          const float* __restrict__ a_src, const float* __restrict__ a_dst,
          float* __restrict__ es, float* __restrict__ ed) {
    extern __shared__ float smem[];
    float* As_hi = smem;
    float* As_lo = smem + 2 * A_ELEMS;
    float* Bs_hi = smem + 4 * A_ELEMS;
    float* Bs_lo = smem + 4 * A_ELEMS + 2 * B_ELEMS;

    const int tid = threadIdx.x;
    const int lane = tid & 31, wid = tid >> 5;
    const int warp_m = wid & 1, warp_n = wid >> 1;
    const int g = lane >> 2, t = lane & 3;
    const int wm0 = warp_m * 64, wn0 = warp_n * 32;
    const int row0 = blockIdx.y * 128;
    const int col0 = blockIdx.x * 128;

    const int arow0 = tid >> 2, ac0 = (tid & 3) << 2;
    const int arow1 = arow0 + 64;
    const int brow0 = tid >> 5, bc0 = (tid & 31) << 2;
    const int brow1 = brow0 + 8;

    // smem byte addresses for this thread's B cp.async targets
    const uint32_t bh0_s = smem_u32(&Bs_hi[brow0 * BSTR + bc0]);
    const uint32_t bh1_s = smem_u32(&Bs_hi[brow1 * BSTR + bc0]);
    const uint32_t bl0_s = smem_u32(&Bs_lo[brow0 * BSTR + bc0]);
    const uint32_t bl1_s = smem_u32(&Bs_lo[brow1 * BSTR + bc0]);
    const uint32_t bstep = B_ELEMS * 4;   // byte offset between buffers

    float4 acc[4][4];
#pragma unroll
    for (int i = 0; i < 4; i++)
#pragma unroll
        for (int j = 0; j < 4; j++) acc[i][j] = make_float4(0.f, 0.f, 0.f, 0.f);

    const int ntiles = K >> 4;
    float4 pa0, pa1;
    pa0 = *(const float4*)&A[(size_t)(row0 + arow0) * K + ac0];
    pa1 = *(const float4*)&A[(size_t)(row0 + arow1) * K + ac0];
    cpasync16(bh0_s, &Bh[(size_t)brow0 * N + col0 + bc0]);
    cpasync16(bh1_s, &Bh[(size_t)brow1 * N + col0 + bc0]);
    cpasync16(bl0_s, &Bl[(size_t)brow0 * N + col0 + bc0]);
    cpasync16(bl1_s, &Bl[(size_t)brow1 * N + col0 + bc0]);
    CP_COMMIT();
    {
        float4 h, l;
        split4(pa0, h, l);
        *(float4*)&As_hi[arow0 * ASTR + ac0] = h;
        *(float4*)&As_lo[arow0 * ASTR + ac0] = l;
        split4(pa1, h, l);
        *(float4*)&As_hi[arow1 * ASTR + ac0] = h;
        *(float4*)&As_lo[arow1 * ASTR + ac0] = l;
    }
    CP_WAIT0();
    __syncthreads();

    int buf = 0;
    for (int kt = 0; kt < ntiles; kt++) {
        const int nb = buf ^ 1;
        if (kt + 1 < ntiles) {
            const int k0 = (kt + 1) << 4;
            pa0 = *(const float4*)&A[(size_t)(row0 + arow0) * K + k0 + ac0];
            pa1 = *(const float4*)&A[(size_t)(row0 + arow1) * K + k0 + ac0];
            cpasync16(bh0_s + nb * bstep, &Bh[(size_t)(k0 + brow0) * N + col0 + bc0]);
            cpasync16(bh1_s + nb * bstep, &Bh[(size_t)(k0 + brow1) * N + col0 + bc0]);
            cpasync16(bl0_s + nb * bstep, &Bl[(size_t)(k0 + brow0) * N + col0 + bc0]);
            cpasync16(bl1_s + nb * bstep, &Bl[(size_t)(k0 + brow1) * N + col0 + bc0]);
            CP_COMMIT();
        }
        const uint32_t* AhS = (const uint32_t*)(As_hi + buf * A_ELEMS);
        const uint32_t* AlS = (const uint32_t*)(As_lo + buf * A_ELEMS);
        const uint32_t* BhS = (const uint32_t*)(Bs_hi + buf * B_ELEMS);
        const uint32_t* BlS = (const uint32_t*)(Bs_lo + buf * B_ELEMS);
#pragma unroll
        for (int k8 = 0; k8 < 16; k8 += 8) {
            uint32_t af[4][4], bh[4][2], bl[4][2];
#pragma unroll
            for (int nt = 0; nt < 4; nt++) {
                const int c = wn0 + nt * 8 + g;
                bh[nt][0] = BhS[(k8 + t) * BSTR + c];
                bh[nt][1] = BhS[(k8 + t + 4) * BSTR + c];
                bl[nt][0] = BlS[(k8 + t) * BSTR + c];
                bl[nt][1] = BlS[(k8 + t + 4) * BSTR + c];
            }
#pragma unroll
            for (int mt = 0; mt < 4; mt++) {
                const int r = wm0 + mt * 16 + g;
                af[mt][0] = AhS[r * ASTR + k8 + t];
                af[mt][1] = AhS[(r + 8) * ASTR + k8 + t];
                af[mt][2] = AhS[r * ASTR + k8 + t + 4];
                af[mt][3] = AhS[(r + 8) * ASTR + k8 + t + 4];
            }
#pragma unroll
            for (int mt = 0; mt < 4; mt++)
#pragma unroll
                for (int nt = 0; nt < 4; nt++) {
                    mma8(acc[mt][nt], af[mt], bh[nt]);
                    mma8(acc[mt][nt], af[mt], bl[nt]);
                }
#pragma unroll
            for (int mt = 0; mt < 4; mt++) {
                const int r = wm0 + mt * 16 + g;
                af[mt][0] = AlS[r * ASTR + k8 + t];
                af[mt][1] = AlS[(r + 8) * ASTR + k8 + t];
                af[mt][2] = AlS[r * ASTR + k8 + t + 4];
                af[mt][3] = AlS[(r + 8) * ASTR + k8 + t + 4];
            }
#pragma unroll
            for (int mt = 0; mt < 4; mt++)
#pragma unroll
                for (int nt = 0; nt < 4; nt++)
                    mma8(acc[mt][nt], af[mt], bh[nt]);
        }
        if (kt + 1 < ntiles) {
            float* Ah2 = As_hi + nb * A_ELEMS;
            float* Al2 = As_lo + nb * A_ELEMS;
            float4 h, l;
            split4(pa0, h, l);
            *(float4*)&Ah2[arow0 * ASTR + ac0] = h;
            *(float4*)&Al2[arow0 * ASTR + ac0] = l;
            split4(pa1, h, l);
            *(float4*)&Ah2[arow1 * ASTR + ac0] = h;
            *(float4*)&Al2[arow1 * ASTR + ac0] = l;
            CP_WAIT0();
            __syncthreads();
            buf = nb;
        }
    }

    // store C (+bias)
#pragma unroll
    for (int nt = 0; nt < 4; nt++) {
        const int c = col0 + wn0 + nt * 8 + 2 * t;
        float2 bv = make_float2(0.f, 0.f);
        if (bias) bv = *(const float2*)&bias[c];
#pragma unroll
        for (int mt = 0; mt < 4; mt++) {
            const int r = row0 + wm0 + mt * 16 + g;
            float2 lo2 = make_float2(acc[mt][nt].x + bv.x, acc[mt][nt].y + bv.y);
            float2 hi2 = make_float2(acc[mt][nt].z + bv.x, acc[mt][nt].w + bv.y);
            *(float2*)&Cm[(size_t)r * N + c] = lo2;
            *(float2*)&Cm[(size_t)(r + 8) * N + c] = hi2;
        }
    }

    // ---- fused es/ed epilogue (GAT layer GEMMs only) ----
    if (a_src) {
        __syncthreads();
        float* es_s = As_hi;
        float* ed_s = As_hi + 256;
        for (int i = tid; i < 512; i += 256) As_hi[i] = 0.f;
        __syncthreads();
        const int lh = wn0 >> 6;
        float asv[4][2], adv[4][2];
#pragma unroll
        for (int nt = 0; nt < 4; nt++) {
            const int gc = col0 + wn0 + nt * 8 + 2 * t;
            asv[nt][0] = a_src[gc];     asv[nt][1] = a_src[gc + 1];
            adv[nt][0] = a_dst[gc];     adv[nt][1] = a_dst[gc + 1];
        }
#pragma unroll
        for (int mt = 0; mt < 4; mt++) {
            float se1 = 0.f, de1 = 0.f, se2 = 0.f, de2 = 0.f;
#pragma unroll
            for (int nt = 0; nt < 4; nt++) {
                se1 += acc[mt][nt].x * asv[nt][0] + acc[mt][nt].y * asv[nt][1];
                de1 += acc[mt][nt].x * adv[nt][0] + acc[mt][nt].y * adv[nt][1];
                se2 += acc[mt][nt].z * asv[nt][0] + acc[mt][nt].w * asv[nt][1];
                de2 += acc[mt][nt].z * adv[nt][0] + acc[mt][nt].w * adv[nt][1];
            }
#pragma unroll
            for (int m = 1; m < 4; m <<= 1) {
                se1 += __shfl_xor_sync(0xffffffffu, se1, m);
                de1 += __shfl_xor_sync(0xffffffffu, de1, m);
                se2 += __shfl_xor_sync(0xffffffffu, se2, m);
                de2 += __shfl_xor_sync(0xffffffffu, de2, m);
            }
            if (t == 0) {
                const int r1 = wm0 + mt * 16 + g;
                atomicAdd(&es_s[r1 * 2 + lh], se1);
                atomicAdd(&ed_s[r1 * 2 + lh], de1);
                atomicAdd(&es_s[(r1 + 8) * 2 + lh], se2);
                atomicAdd(&ed_s[(r1 + 8) * 2 + lh], de2);
            }
        }
        __syncthreads();
        const int r = tid >> 1, l = tid & 1;
        const int h0 = col0 >> 6;
        es[(size_t)(row0 + r) * HH + h0 + l] = es_s[r * 2 + l];
        ed[(size_t)(row0 + r) * HH + h0 + l] = ed_s[r * 2 + l];
    }
}

// ---------------- fused softmax + aggregate + bias + ELU (R10-proven) -------
__global__ void __launch_bounds__(256)
gat_fused(const int* __restrict__ off, const int* __restrict__ csrc,
          const float* __restrict__ es, const float* __restrict__ ed,
          const float* __restrict__ hlin, const float* __restrict__ bias,
          float* __restrict__ out) {
    const int n = (blockIdx.x * blockDim.x + threadIdx.x) >> 5;
    const int lane = threadIdx.x & 31;
    if (n >= NN) return;

    const float4 edv = ((const float4*)ed)[n];
    const float4 esv = ((const float4*)es)[n];
    const float xs0 = __expf(leaky(esv.x + edv.x));
    const float xs1 = __expf(leaky(esv.y + edv.y));
    const float xs2 = __expf(leaky(esv.z + edv.z));
    const float xs3 = __expf(leaky(esv.w + edv.w));

    const int hi = lane >> 4;
    const float4* hn = (const float4*)(hlin + (size_t)n * CC);
    float4 acc0 = hn[lane];
    float4 acc1 = hn[32 + lane];
    const float sa0 = hi ? xs1 : xs0;
    const float sa1 = hi ? xs3 : xs2;
    acc0.x *= sa0; acc0.y *= sa0; acc0.z *= sa0; acc0.w *= sa0;
    acc1.x *= sa1; acc1.y *= sa1; acc1.z *= sa1; acc1.w *= sa1;

    float ts0 = 0.f, ts1 = 0.f, ts2 = 0.f, ts3 = 0.f;
    const int o0 = off[n], o1 = off[n + 1];
    for (int base = o0; base < o1; base += 32) {
        const int cnt = min(32, o1 - base);
        int s = 0;
        float t0 = 0.f, t1 = 0.f, t2 = 0.f, t3 = 0.f;
        if (lane < cnt) {
            s = csrc[base + lane];
            const float4 ess = ((const float4*)es)[s];
            t0 = __expf(leaky(ess.x + edv.x));
            t1 = __expf(leaky(ess.y + edv.y));
            t2 = __expf(leaky(ess.z + edv.z));
            t3 = __expf(leaky(ess.w + edv.w));
        }
        ts0 += t0; ts1 += t1; ts2 += t2; ts3 += t3;

        int se = __shfl_sync(0xffffffffu, s, 0);
        const float4* hs = (const float4*)(hlin + (size_t)se * CC);
        float4 v0n = hs[lane], v1n = hs[32 + lane];
        for (int e = 0; e < cnt; e++) {
            const float4 v0 = v0n, v1 = v1n;
            const float w0 = __shfl_sync(0xffffffffu, t0, e);
            const float w1 = __shfl_sync(0xffffffffu, t1, e);
            const float w2 = __shfl_sync(0xffffffffu, t2, e);
            const float w3 = __shfl_sync(0xffffffffu, t3, e);
            if (e + 1 < cnt) {
                se = __shfl_sync(0xffffffffu, s, e + 1);
                const float4* hsn = (const float4*)(hlin + (size_t)se * CC);
                v0n = hsn[lane]; v1n = hsn[32 + lane];
            }
            const float aw0 = hi ? w1 : w0;
            const float aw1 = hi ? w3 : w2;
            acc0.x += aw0 * v0.x; acc0.y += aw0 * v0.y;
            acc0.z += aw0 * v0.z; acc0.w += aw0 * v0.w;
            acc1.x += aw1 * v1.x; acc1.y += aw1 * v1.y;
            acc1.z += aw1 * v1.z; acc1.w += aw1 * v1.w;
        }
    }
#pragma unroll
    for (int o = 16; o; o >>= 1) {
        ts0 += __shfl_xor_sync(0xffffffffu, ts0, o);
        ts1 += __shfl_xor_sync(0xffffffffu, ts1, o);
        ts2 += __shfl_xor_sync(0xffffffffu, ts2, o);
        ts3 += __shfl_xor_sync(0xffffffffu, ts3, o);
    }
    const float di0 = 1.f / (xs0 + ts0 + 1e-16f);
    const float di1 = 1.f / (xs1 + ts1 + 1e-16f);
    const float di2 = 1.f / (xs2 + ts2 + 1e-16f);
    const float di3 = 1.f / (xs3 + ts3 + 1e-16f);
    const float d0 = hi ? di1 : di0;
    const float d1 = hi ? di3 : di2;

    const float4 bv0 = ((const float4*)bias)[lane];
    const float4 bv1 = ((const float4*)bias)[32 + lane];
    float4 o0v, o1v;
    o0v.x = acc0.x * d0 + bv0.x; o0v.y = acc0.y * d0 + bv0.y;
    o0v.z = acc0.z * d0 + bv0.z; o0v.w = acc0.w * d0 + bv0.w;
    o1v.x = acc1.x * d1 + bv1.x; o1v.y = acc1.y * d1 + bv1.y;
    o1v.z = acc1.z * d1 + bv1.z; o1v.w = acc1.w * d1 + bv1.w;
    o0v.x = o0v.x > 0.f ? o0v.x : (__expf(o0v.x) - 1.f);
    o0v.y = o0v.y > 0.f ? o0v.y : (__expf(o0v.y) - 1.f);
    o0v.z = o0v.z > 0.f ? o0v.z : (__expf(o0v.z) - 1.f);
    o0v.w = o0v.w > 0.f ? o0v.w : (__expf(o0v.w) - 1.f);
    o1v.x = o1v.x > 0.f ? o1v.x : (__expf(o1v.x) - 1.f);
    o1v.y = o1v.y > 0.f ? o1v.y : (__expf(o1v.y) - 1.f);
    o1v.z = o1v.z > 0.f ? o1v.z : (__expf(o1v.z) - 1.f);
    o1v.w = o1v.w > 0.f ? o1v.w : (__expf(o1v.w) - 1.f);
    ((float4*)out)[(size_t)n * 64 + lane]      = o0v;
    ((float4*)out)[(size_t)n * 64 + 32 + lane] = o1v;
}

// ---------------- fused pooling: score + top-k + gather ---------------------
template <int NPB, int KSEL>
__global__ void pool_fused(const float* __restrict__ X, const float* __restrict__ sw,
                           float* __restrict__ selb) {
    __shared__ float sv[NPB];
    __shared__ int si[NPB];
    const int b = blockIdx.x, t = threadIdx.x;
    const int wid = t >> 5, lane = t & 31;

#pragma unroll
    for (int rr = 0; rr < 32; rr++) {
        const int local = wid * 32 + rr;
        const float* xp = X + (size_t)(b * NPB + local) * CC;
        float s = 0.f;
#pragma unroll
        for (int c = 0; c < CC / 32; c++) s += xp[lane + c * 32] * sw[lane + c * 32];
#pragma unroll
        for (int o = 16; o; o >>= 1) s += __shfl_xor_sync(0xffffffffu, s, o);
        if (lane == 0) { sv[local] = s; si[local] = local; }
    }
    __syncthreads();

    for (int k = 2; k <= NPB; k <<= 1) {
        for (int j = k >> 1; j > 0; j >>= 1) {
            const int ixj = t ^ j;
            if (ixj > t) {
                const bool desc = ((t & k) == 0);
                const float a = sv[t], c = sv[ixj];
                if ((a < c) == desc) {
                    sv[t] = c; sv[ixj] = a;
                    const int tmp = si[t]; si[t] = si[ixj]; si[ixj] = tmp;
                }
            }
            __syncthreads();
        }
    }

    for (int idx = t; idx < KSEL * 64; idx += NPB) {
        const int r = idx >> 6, q = idx & 63;
        const int src = b * NPB + si[r];
        ((float4*)selb)[(size_t)(b * KSEL + r) * 64 + q] =
            ((const float4*)X)[(size_t)src * 64 + q];
    }
}

// ---------------- fused readout: mean + fc1(relu) + fc2 + log_softmax -------
__global__ void __launch_bounds__(256)
readout_fused(const float* __restrict__ X, const float* __restrict__ c1w,
              const float* __restrict__ c1b, const float* __restrict__ c2w,
              const float* __restrict__ c2b, float* __restrict__ out) {
    __shared__ float gm[CC];
    __shared__ float f1[64];
    const int b = blockIdx.x, t = threadIdx.x;
    const int wid = t >> 5, lane = t & 31;

    float s = 0.f;
    const float* xp = X + (size_t)b * K2 * CC + t;
#pragma unroll 4
    for (int r = 0; r < K2; r++) s += xp[r * CC];
    gm[t] = s * (1.f / K2);
    __syncthreads();

#pragma unroll
    for (int oo = 0; oo < 8; oo++) {
        const int o = wid * 8 + oo;
        float acc = 0.f;
#pragma unroll
        for (int c = 0; c < CC / 32; c++)
            acc += gm[lane + c * 32] * c1w[(lane + c * 32) * 64 + o];
#pragma unroll
        for (int off = 16; off; off >>= 1) acc += __shfl_xor_sync(0xffffffffu, acc, off);
        if (lane == 0) {
            const float v = acc + c1b[o];
            f1[o] = v > 0.f ? v : 0.f;
        }
    }
    __syncthreads();

    if (wid == 0) {
        float l0 = 0.f, l1 = 0.f;
#pragma unroll
        for (int k = lane; k < 64; k += 32) {
            const float v = f1[k];
            l0 += v * c2w[k * 2 + 0];
            l1 += v * c2w[k * 2 + 1];
        }
#pragma unroll
        for (int off = 16; off; off >>= 1) {
            l0 += __shfl_xor_sync(0xffffffffu, l0, off);
            l1 += __shfl_xor_sync(0xffffffffu, l1, off);
        }
        if (lane == 0) {
            l0 += c2b[0]; l1 += c2b[1];
            const float mm = fmaxf(l0, l1);
            const float lse = mm + logf(__expf(l0 - mm) + __expf(l1 - mm));
            out[b * 2 + 0] = l0 - lse;
            out[b * 2 + 1] = l1 - lse;
        }
    }
}

// ---------------- host orchestration ----------------------------------------
static float* sym(const void* s) {
    void* p = nullptr;
    cudaGetSymbolAddress(&p, (const void*)s);
    return (float*)p;
}

extern "C" void kernel_launch(void* const* d_in, const int* in_sizes, int n_in,
                              void* d_out, int out_size) {
    const float* x      = (const float*)d_in[0];
    const int*   ei     = (const int*)  d_in[1];
    const float* W1     = (const float*)d_in[3];
    const float* asrc1  = (const float*)d_in[4];
    const float* adst1  = (const float*)d_in[5];
    const float* b1     = (const float*)d_in[6];
    const float* W2     = (const float*)d_in[7];
    const float* asrc2  = (const float*)d_in[8];
    const float* adst2  = (const float*)d_in[9];
    const float* b2     = (const float*)d_in[10];
    const float* p1_sw  = (const float*)d_in[11];
    const float* p1_tw  = (const float*)d_in[13];
    const float* p1_tb  = (const float*)d_in[14];
    const float* p2_sw  = (const float*)d_in[15];
    const float* p2_tw  = (const float*)d_in[17];
    const float* p2_tb  = (const float*)d_in[18];
    const float* c1w    = (const float*)d_in[19];
    const float* c1b    = (const float*)d_in[20];
    const float* c2w    = (const float*)d_in[21];
    const float* c2b    = (const float*)d_in[22];
    float* out = (float*)d_out;

    float* hlin  = sym(g_hlin);
    float* hout  = sym(g_hout);
    float* es    = sym(g_es);
    float* ed    = sym(g_ed);
    int*   off   = (int*)sym(g_off);
    int*   csrc  = (int*)sym(g_csrc);
    float* selb  = sym(g_sel);
    float* pool1 = sym(g_pool1);
    float* pool2 = sym(g_pool2);
    float* w1h = sym(g_w1h), *w1l = sym(g_w1l);
    float* w2h = sym(g_w2h), *w2l = sym(g_w2l);
    float* p1h = sym(g_p1h), *p1l = sym(g_p1l);
    float* p2h = sym(g_p2h), *p2l = sym(g_p2l);

    cudaFuncSetAttribute(tf32_gemm, cudaFuncAttributeMaxDynamicSharedMemorySize,
                         GEMM_SMEM);

    dim3 t256(256);

    // ---- merged prep: CSR build + weight split (one launch) ----
    prep_kernel<<<BB + 224, t256>>>(ei, W1, W2, p1_tw, p2_tw,
                                    w1h, w1l, w2h, w2l, p1h, p1l, p2h, p2l);

    // ---- GAT layer 1 (GEMM emits es/ed in epilogue) ----
    tf32_gemm<<<dim3(CC / 128, NN / 128), t256, GEMM_SMEM>>>(
        x, w1h, w1l, nullptr, hlin, NN, CC, FIN, asrc1, adst1, es, ed);
    gat_fused<<<(NN * 32) / 256, t256>>>(off, csrc, es, ed, hlin, b1, hout);

    // ---- GAT layer 2 ----
    tf32_gemm<<<dim3(CC / 128, NN / 128), t256, GEMM_SMEM>>>(
        hout, w2h, w2l, nullptr, hlin, NN, CC, CC, asrc2, adst2, es, ed);
    gat_fused<<<(NN * 32) / 256, t256>>>(off, csrc, es, ed, hlin, b2, hout);

    // ---- Pool 1 (top-256 of 512 per graph) ----
    pool_fused<NPG, K1><<<BB, NPG>>>(hout, p1_sw, selb);
    tf32_gemm<<<dim3(CC / 128, (BB * K1) / 128), t256, GEMM_SMEM>>>(
        selb, p1h, p1l, p1_tb, pool1, BB * K1, CC, CC,
        nullptr, nullptr, nullptr, nullptr);

    // ---- Pool 2 (top-128 of 256 per graph) ----
    pool_fused<K1, K2><<<BB, K1>>>(pool1, p2_sw, selb);
    tf32_gemm<<<dim3(CC / 128, (BB * K2) / 128), t256, GEMM_SMEM>>>(
        selb, p2h, p2l, p2_tb, pool2, BB * K2, CC, CC,
        nullptr, nullptr, nullptr, nullptr);

    // ---- readout ----
    readout_fused<<<BB, t256>>>(pool2, c1w, c1b, c2w, c2b, out);
}